// round 7
// baseline (speedup 1.0000x reference)
#include <cuda_runtime.h>
#include <cuda_bf16.h>
#include <math.h>

// Problem dims (fixed)
#define BB 2
#define QQ 2048
#define CQd 512
#define NH 8
#define HD 64
#define MROWS (BB * QQ)   // 4096
#define NCOLS 2048        // 3*H*D (qkv) + H*D (gate)
#define KDIM 512

typedef unsigned long long u64;

__device__ __forceinline__ void fma2(u64 &d, u64 a, u64 b) {
    asm("fma.rn.f32x2 %0, %1, %2, %0;" : "+l"(d) : "l"(a), "l"(b));
}
__device__ __forceinline__ u64 mul2(u64 a, u64 b) {
    u64 d; asm("mul.rn.f32x2 %0, %1, %2;" : "=l"(d) : "l"(a), "l"(b)); return d;
}
__device__ __forceinline__ u64 dup2(float x) {
    u64 d; asm("mov.b64 %0, {%1, %1};" : "=l"(d) : "f"(x)); return d;
}
__device__ __forceinline__ float lo2(u64 v) { return __uint_as_float((unsigned)v); }
__device__ __forceinline__ float hi2(u64 v) { return __uint_as_float((unsigned)(v >> 32)); }

// Scratch (no allocations allowed -> device globals)
__device__ float g_qkvg[(size_t)MROWS * NCOLS]; // q(scaled)|k|v|sigmoid(gate)
__device__ float g_o[(size_t)MROWS * 512];      // gated attention output

// ---------------------------------------------------------------------------
// Kernel 1: fused QKV + gate projection, f32x2 packed along n.
// As2: [k][2m] duplicated layout; Bs: [k][n] natural (n-pairs natural).
// ---------------------------------------------------------------------------
__global__ __launch_bounds__(256) void k_gemm_qkvg(
    const float* __restrict__ A,
    const float* __restrict__ Wqkv,
    const float* __restrict__ Wg,
    const float* __restrict__ bg)
{
    __shared__ float As2[16 * 260];  // k-major, rows duplicated: [k][2*m]
    __shared__ float Bs[16 * 132];   // k-major: [k][n]
    const int tid = threadIdx.x;
    const int tx = tid & 15;
    const int ty = tid >> 4;
    const int m0 = blockIdx.y * 128;
    const int n0 = blockIdx.x * 128;

    const float* Asrc = A + (size_t)m0 * KDIM;
    const float* Bsrc = (n0 < 1536) ? (Wqkv + (size_t)n0 * KDIM)
                                    : (Wg + (size_t)(n0 - 1536) * KDIM);

    const int lr0 = tid >> 2;        // 0..63
    const int lk  = (tid & 3) << 2;  // 0,4,8,12

    u64 acc2[8][4];
#pragma unroll
    for (int i = 0; i < 8; ++i)
#pragma unroll
        for (int j = 0; j < 4; ++j) acc2[i][j] = 0ull;

    float4 a0 = *(const float4*)(Asrc + (size_t)lr0 * KDIM + lk);
    float4 a1 = *(const float4*)(Asrc + (size_t)(lr0 + 64) * KDIM + lk);
    float4 b0 = *(const float4*)(Bsrc + (size_t)lr0 * KDIM + lk);
    float4 b1 = *(const float4*)(Bsrc + (size_t)(lr0 + 64) * KDIM + lk);

    for (int kt = 0; kt < KDIM / 16; ++kt) {
        // As2: duplicated stores (STS.64 of {v,v})
        {
            const float av0[4] = {a0.x, a0.y, a0.z, a0.w};
            const float av1[4] = {a1.x, a1.y, a1.z, a1.w};
#pragma unroll
            for (int c = 0; c < 4; ++c) {
                *(float2*)(&As2[(lk + c) * 260 + lr0 * 2]) = make_float2(av0[c], av0[c]);
                *(float2*)(&As2[(lk + c) * 260 + 128 + lr0 * 2]) = make_float2(av1[c], av1[c]);
            }
        }
        Bs[(lk + 0) * 132 + lr0] = b0.x;
        Bs[(lk + 1) * 132 + lr0] = b0.y;
        Bs[(lk + 2) * 132 + lr0] = b0.z;
        Bs[(lk + 3) * 132 + lr0] = b0.w;
        Bs[(lk + 0) * 132 + lr0 + 64] = b1.x;
        Bs[(lk + 1) * 132 + lr0 + 64] = b1.y;
        Bs[(lk + 2) * 132 + lr0 + 64] = b1.z;
        Bs[(lk + 3) * 132 + lr0 + 64] = b1.w;
        __syncthreads();

        if (kt < KDIM / 16 - 1) {
            const int kc = (kt + 1) * 16 + lk;
            a0 = *(const float4*)(Asrc + (size_t)lr0 * KDIM + kc);
            a1 = *(const float4*)(Asrc + (size_t)(lr0 + 64) * KDIM + kc);
            b0 = *(const float4*)(Bsrc + (size_t)lr0 * KDIM + kc);
            b1 = *(const float4*)(Bsrc + (size_t)(lr0 + 64) * KDIM + kc);
        }

#pragma unroll
        for (int k = 0; k < 16; ++k) {
            ulonglong2 a01 = *(const ulonglong2*)(&As2[k * 260 + ty * 8]);
            ulonglong2 a23 = *(const ulonglong2*)(&As2[k * 260 + ty * 8 + 4]);
            ulonglong2 a45 = *(const ulonglong2*)(&As2[k * 260 + 128 + ty * 8]);
            ulonglong2 a67 = *(const ulonglong2*)(&As2[k * 260 + 132 + ty * 8]);
            ulonglong2 b03 = *(const ulonglong2*)(&Bs[k * 132 + tx * 4]);
            ulonglong2 b47 = *(const ulonglong2*)(&Bs[k * 132 + 64 + tx * 4]);
            u64 ar[8] = {a01.x, a01.y, a23.x, a23.y, a45.x, a45.y, a67.x, a67.y};
            u64 br[4] = {b03.x, b03.y, b47.x, b47.y};
#pragma unroll
            for (int i = 0; i < 8; ++i)
#pragma unroll
                for (int j = 0; j < 4; ++j)
                    fma2(acc2[i][j], ar[i], br[j]);
        }
        __syncthreads();
    }

    const float qscale = (n0 < 512) ? 0.125f : 1.0f;  // 1/sqrt(64)
    const bool gatep = (n0 >= 1536);
#pragma unroll
    for (int i = 0; i < 8; ++i) {
        const int m = m0 + ((i < 4) ? (ty * 4 + i) : (64 + ty * 4 + (i - 4)));
#pragma unroll
        for (int jh = 0; jh < 2; ++jh) {
            const int n = n0 + jh * 64 + tx * 4;
            const u64 p0 = acc2[i][jh * 2 + 0];
            const u64 p1 = acc2[i][jh * 2 + 1];
            float v[4] = {lo2(p0) * qscale, hi2(p0) * qscale,
                          lo2(p1) * qscale, hi2(p1) * qscale};
            if (gatep) {
#pragma unroll
                for (int c = 0; c < 4; ++c) {
                    const float x = v[c] + bg[n - 1536 + c];
                    v[c] = 1.0f / (1.0f + __expf(-x));
                }
            }
            *(float4*)(&g_qkvg[(size_t)m * NCOLS + n]) = make_float4(v[0], v[1], v[2], v[3]);
        }
    }
}

// ---------------------------------------------------------------------------
// Kernel 2: flash attention, f32x2 packed along the reduction dim.
// Qs/Ks: natural [r][d] with XOR swizzle; Vt: [dv][j] transposed + swizzle;
// P: natural [r][j] (reuses Ks buffer). O accumulator stays packed (j parity).
// ---------------------------------------------------------------------------
#define QT 64

__global__ __launch_bounds__(256) void k_flash(const float* __restrict__ bias)
{
    __shared__ float Qs[64 * 64];
    __shared__ float KP[64 * 64];   // K (swizzled) then P (natural)
    __shared__ float Vt[64 * 64];   // V transposed [dv][j], swizzled

    const int tid = threadIdx.x;
    const int tx = tid & 15;
    const int ty = tid >> 4;
    const int q0 = blockIdx.x * QT;
    const int h  = blockIdx.y;
    const int b  = blockIdx.z;

    const size_t rbase = (size_t)b * QQ;
    const float* biasb = bias + (size_t)b * QQ * QQ;
    const int hq = h * HD;

    // Load Q tile: natural layout, XOR-swizzled 16B slots. (pre-scaled by 1/8)
#pragma unroll
    for (int it = 0; it < 4; ++it) {
        const int a = tid + it * 256;
        const int r = a >> 4;
        const int dq = a & 15;
        float4 v = *(const float4*)(&g_qkvg[(rbase + q0 + r) * NCOLS + hq + dq * 4]);
        *(float4*)(&Qs[r * 64 + ((dq ^ (r >> 2)) & 15) * 4]) = v;
    }

    float mrow[4], lrow[4];
    u64 o2[4][4];
#pragma unroll
    for (int i = 0; i < 4; ++i) {
        mrow[i] = -3.0e38f;
        lrow[i] = 0.f;
#pragma unroll
        for (int c = 0; c < 4; ++c) o2[i][c] = 0ull;
    }

    for (int kt = 0; kt < QQ / QT; ++kt) {
        const int k0 = kt * QT;
        __syncthreads();  // prev iter's P/V reads complete
        // Load K (vectorized swizzled stores) and V (transposed scalar stores)
#pragma unroll
        for (int it = 0; it < 4; ++it) {
            const int a = tid + it * 256;
            const int r = a >> 4;
            const int dq = a & 15;
            const float* src = &g_qkvg[(rbase + k0 + r) * NCOLS];
            float4 kv = *(const float4*)(src + 512 + hq + dq * 4);
            *(float4*)(&KP[r * 64 + ((dq ^ (r >> 2)) & 15) * 4]) = kv;
            float4 vv = *(const float4*)(src + 1024 + hq + dq * 4);
            const float vvv[4] = {vv.x, vv.y, vv.z, vv.w};
#pragma unroll
            for (int c = 0; c < 4; ++c) {
                const int dv = dq * 4 + c;
                Vt[dv * 64 + (((r >> 2) ^ (dv >> 2)) & 15) * 4 + (r & 3)] = vvv[c];
            }
        }
        __syncthreads();

        // S = Q K^T : pairs packed along d
        u64 s2[4][4];
#pragma unroll
        for (int i = 0; i < 4; ++i)
#pragma unroll
            for (int j = 0; j < 4; ++j) s2[i][j] = 0ull;
#pragma unroll
        for (int dq = 0; dq < 16; ++dq) {
            const int sa = ((dq ^ ty) & 15) * 4;
            const int sb = ((dq ^ tx) & 15) * 4;
            ulonglong2 qa[4], kb[4];
#pragma unroll
            for (int i = 0; i < 4; ++i)
                qa[i] = *(const ulonglong2*)(&Qs[(ty * 4 + i) * 64 + sa]);
#pragma unroll
            for (int j = 0; j < 4; ++j)
                kb[j] = *(const ulonglong2*)(&KP[(tx * 4 + j) * 64 + sb]);
#pragma unroll
            for (int i = 0; i < 4; ++i)
#pragma unroll
                for (int j = 0; j < 4; ++j) {
                    fma2(s2[i][j], qa[i].x, kb[j].x);
                    fma2(s2[i][j], qa[i].y, kb[j].y);
                }
        }

        // combine parities + bias
        float s[4][4];
#pragma unroll
        for (int i = 0; i < 4; ++i) {
            float4 bb = *(const float4*)(biasb + (size_t)(q0 + ty * 4 + i) * QQ + k0 + tx * 4);
            s[i][0] = lo2(s2[i][0]) + hi2(s2[i][0]) + bb.x;
            s[i][1] = lo2(s2[i][1]) + hi2(s2[i][1]) + bb.y;
            s[i][2] = lo2(s2[i][2]) + hi2(s2[i][2]) + bb.z;
            s[i][3] = lo2(s2[i][3]) + hi2(s2[i][3]) + bb.w;
        }
        // online softmax (row group = 16 lanes)
#pragma unroll
        for (int i = 0; i < 4; ++i) {
            float mx = fmaxf(fmaxf(s[i][0], s[i][1]), fmaxf(s[i][2], s[i][3]));
#pragma unroll
            for (int o = 8; o > 0; o >>= 1)
                mx = fmaxf(mx, __shfl_xor_sync(0xffffffffu, mx, o));
            const float mnew = fmaxf(mrow[i], mx);
            const float p0 = __expf(s[i][0] - mnew);
            const float p1 = __expf(s[i][1] - mnew);
            const float p2 = __expf(s[i][2] - mnew);
            const float p3 = __expf(s[i][3] - mnew);
            float rs = (p0 + p1) + (p2 + p3);
#pragma unroll
            for (int o = 8; o > 0; o >>= 1)
                rs += __shfl_xor_sync(0xffffffffu, rs, o);
            const float scale = __expf(mrow[i] - mnew);
            lrow[i] = lrow[i] * scale + rs;
            mrow[i] = mnew;
            const u64 scp = dup2(scale);
            o2[i][0] = mul2(o2[i][0], scp);
            o2[i][1] = mul2(o2[i][1], scp);
            o2[i][2] = mul2(o2[i][2], scp);
            o2[i][3] = mul2(o2[i][3], scp);
            s[i][0] = p0; s[i][1] = p1; s[i][2] = p2; s[i][3] = p3;
        }
        __syncthreads();  // K reads done before P overwrites the buffer
        // store P natural [r][j] (conflict-free float4)
#pragma unroll
        for (int i = 0; i < 4; ++i)
            *(float4*)(&KP[(ty * 4 + i) * 64 + tx * 4]) =
                make_float4(s[i][0], s[i][1], s[i][2], s[i][3]);
        __syncthreads();

        // O += P V : pairs packed along j
#pragma unroll
        for (int jq = 0; jq < 16; ++jq) {
            const int sv = ((jq ^ tx) & 15) * 4;
            ulonglong2 pa[4], vb[4];
#pragma unroll
            for (int i = 0; i < 4; ++i)
                pa[i] = *(const ulonglong2*)(&KP[(ty * 4 + i) * 64 + jq * 4]);
#pragma unroll
            for (int c = 0; c < 4; ++c)
                vb[c] = *(const ulonglong2*)(&Vt[(tx * 4 + c) * 64 + sv]);
#pragma unroll
            for (int i = 0; i < 4; ++i)
#pragma unroll
                for (int c = 0; c < 4; ++c) {
                    fma2(o2[i][c], pa[i].x, vb[c].x);
                    fma2(o2[i][c], pa[i].y, vb[c].y);
                }
        }
    }

    // epilogue: combine parities, normalize, sigmoid gate
#pragma unroll
    for (int i = 0; i < 4; ++i) {
        const size_t row = rbase + q0 + ty * 4 + i;
        const float inv = 1.0f / lrow[i];
        float4 g4 = *(const float4*)(&g_qkvg[row * NCOLS + 1536 + hq + tx * 4]);
        float4 o4;
        o4.x = (lo2(o2[i][0]) + hi2(o2[i][0])) * inv * g4.x;
        o4.y = (lo2(o2[i][1]) + hi2(o2[i][1])) * inv * g4.y;
        o4.z = (lo2(o2[i][2]) + hi2(o2[i][2])) * inv * g4.z;
        o4.w = (lo2(o2[i][3]) + hi2(o2[i][3])) * inv * g4.w;
        *(float4*)(&g_o[row * 512 + hq + tx * 4]) = o4;
    }
}

// ---------------------------------------------------------------------------
// Kernel 3: output projection, same f32x2 structure as kernel 1
// ---------------------------------------------------------------------------
__global__ __launch_bounds__(256) void k_gemm_out(
    const float* __restrict__ Wo,
    const float* __restrict__ bo,
    float* __restrict__ out)
{
    __shared__ float As2[16 * 260];
    __shared__ float Bs[16 * 132];
    const int tid = threadIdx.x;
    const int tx = tid & 15;
    const int ty = tid >> 4;
    const int m0 = blockIdx.y * 128;
    const int n0 = blockIdx.x * 128;

    const float* Asrc = g_o + (size_t)m0 * KDIM;
    const float* Bsrc = Wo + (size_t)n0 * KDIM;

    const int lr0 = tid >> 2;
    const int lk  = (tid & 3) << 2;

    u64 acc2[8][4];
#pragma unroll
    for (int i = 0; i < 8; ++i)
#pragma unroll
        for (int j = 0; j < 4; ++j) acc2[i][j] = 0ull;

    float4 a0 = *(const float4*)(Asrc + (size_t)lr0 * KDIM + lk);
    float4 a1 = *(const float4*)(Asrc + (size_t)(lr0 + 64) * KDIM + lk);
    float4 b0 = *(const float4*)(Bsrc + (size_t)lr0 * KDIM + lk);
    float4 b1 = *(const float4*)(Bsrc + (size_t)(lr0 + 64) * KDIM + lk);

    for (int kt = 0; kt < KDIM / 16; ++kt) {
        {
            const float av0[4] = {a0.x, a0.y, a0.z, a0.w};
            const float av1[4] = {a1.x, a1.y, a1.z, a1.w};
#pragma unroll
            for (int c = 0; c < 4; ++c) {
                *(float2*)(&As2[(lk + c) * 260 + lr0 * 2]) = make_float2(av0[c], av0[c]);
                *(float2*)(&As2[(lk + c) * 260 + 128 + lr0 * 2]) = make_float2(av1[c], av1[c]);
            }
        }
        Bs[(lk + 0) * 132 + lr0] = b0.x;
        Bs[(lk + 1) * 132 + lr0] = b0.y;
        Bs[(lk + 2) * 132 + lr0] = b0.z;
        Bs[(lk + 3) * 132 + lr0] = b0.w;
        Bs[(lk + 0) * 132 + lr0 + 64] = b1.x;
        Bs[(lk + 1) * 132 + lr0 + 64] = b1.y;
        Bs[(lk + 2) * 132 + lr0 + 64] = b1.z;
        Bs[(lk + 3) * 132 + lr0 + 64] = b1.w;
        __syncthreads();

        if (kt < KDIM / 16 - 1) {
            const int kc = (kt + 1) * 16 + lk;
            a0 = *(const float4*)(Asrc + (size_t)lr0 * KDIM + kc);
            a1 = *(const float4*)(Asrc + (size_t)(lr0 + 64) * KDIM + kc);
            b0 = *(const float4*)(Bsrc + (size_t)lr0 * KDIM + kc);
            b1 = *(const float4*)(Bsrc + (size_t)(lr0 + 64) * KDIM + kc);
        }

#pragma unroll
        for (int k = 0; k < 16; ++k) {
            ulonglong2 a01 = *(const ulonglong2*)(&As2[k * 260 + ty * 8]);
            ulonglong2 a23 = *(const ulonglong2*)(&As2[k * 260 + ty * 8 + 4]);
            ulonglong2 a45 = *(const ulonglong2*)(&As2[k * 260 + 128 + ty * 8]);
            ulonglong2 a67 = *(const ulonglong2*)(&As2[k * 260 + 132 + ty * 8]);
            ulonglong2 b03 = *(const ulonglong2*)(&Bs[k * 132 + tx * 4]);
            ulonglong2 b47 = *(const ulonglong2*)(&Bs[k * 132 + 64 + tx * 4]);
            u64 ar[8] = {a01.x, a01.y, a23.x, a23.y, a45.x, a45.y, a67.x, a67.y};
            u64 br[4] = {b03.x, b03.y, b47.x, b47.y};
#pragma unroll
            for (int i = 0; i < 8; ++i)
#pragma unroll
                for (int j = 0; j < 4; ++j)
                    fma2(acc2[i][j], ar[i], br[j]);
        }
        __syncthreads();
    }

#pragma unroll
    for (int i = 0; i < 8; ++i) {
        const int m = m0 + ((i < 4) ? (ty * 4 + i) : (64 + ty * 4 + (i - 4)));
#pragma unroll
        for (int jh = 0; jh < 2; ++jh) {
            const int n = n0 + jh * 64 + tx * 4;
            const u64 p0 = acc2[i][jh * 2 + 0];
            const u64 p1 = acc2[i][jh * 2 + 1];
            float4 o4;
            o4.x = lo2(p0) + bo[n + 0];
            o4.y = hi2(p0) + bo[n + 1];
            o4.z = lo2(p1) + bo[n + 2];
            o4.w = hi2(p1) + bo[n + 3];
            *(float4*)(&out[(size_t)m * 512 + n]) = o4;
        }
    }
}

// ---------------------------------------------------------------------------
extern "C" void kernel_launch(void* const* d_in, const int* in_sizes, int n_in,
                              void* d_out, int out_size)
{
    (void)in_sizes; (void)n_in; (void)out_size;
    const float* q_x   = (const float*)d_in[0];
    // d_in[1] = kv_x (unused by the reference)
    const float* bias  = (const float*)d_in[2];
    const float* w_qkv = (const float*)d_in[3];
    const float* w_o   = (const float*)d_in[4];
    const float* b_o   = (const float*)d_in[5];
    const float* w_g   = (const float*)d_in[6];
    const float* b_g   = (const float*)d_in[7];
    float* out = (float*)d_out;

    dim3 g1(NCOLS / 128, MROWS / 128);  // (16, 32)
    k_gemm_qkvg<<<g1, 256>>>(q_x, w_qkv, w_g, b_g);

    dim3 g2(QQ / QT, NH, BB);           // (32, 8, 2)
    k_flash<<<g2, 256>>>(bias);

    dim3 g3(512 / 128, MROWS / 128);    // (4, 32)
    k_gemm_out<<<g3, 256>>>(w_o, b_o, out);
}

// round 12
// speedup vs baseline: 1.4656x; 1.4656x over previous
#include <cuda_runtime.h>
#include <cuda_bf16.h>
#include <math.h>
#include <stdint.h>

// Problem dims (fixed)
#define BB 2
#define QQ 2048
#define CQd 512
#define NH 8
#define HD 64
#define MROWS (BB * QQ)   // 4096
#define NCOLS 2048        // 3*H*D (qkv) + H*D (gate)
#define KDIM 512

// Scratch (no allocations allowed -> device globals)
__device__ float g_qkvg[(size_t)MROWS * NCOLS]; // q(scaled)|k|v|sigmoid(gate)
__device__ float g_o[(size_t)MROWS * 512];      // gated attention output

// ===========================================================================
// Baseline-PTX tensor helpers (sm_80-era: valid on compute_103 base target)
// ===========================================================================
__device__ __forceinline__ uint32_t smem_u32(const void* p) {
    uint32_t a;
    asm("{ .reg .u64 t; cvta.to.shared.u64 t, %1; cvt.u32.u64 %0, t; }"
        : "=r"(a) : "l"(p));
    return a;
}

__device__ __forceinline__ void ldsm4(uint32_t* r, uint32_t addr) {
    asm volatile("ldmatrix.sync.aligned.m8n8.x4.shared.b16 {%0,%1,%2,%3}, [%4];"
                 : "=r"(r[0]), "=r"(r[1]), "=r"(r[2]), "=r"(r[3]) : "r"(addr));
}

__device__ __forceinline__ void mma16816(float* c, const uint32_t* a,
                                         uint32_t b0, uint32_t b1) {
    asm volatile(
        "mma.sync.aligned.m16n8k16.row.col.f32.bf16.bf16.f32 "
        "{%0,%1,%2,%3}, {%4,%5,%6,%7}, {%8,%9}, {%0,%1,%2,%3};"
        : "+f"(c[0]), "+f"(c[1]), "+f"(c[2]), "+f"(c[3])
        : "r"(a[0]), "r"(a[1]), "r"(a[2]), "r"(a[3]), "r"(b0), "r"(b1));
}

// pack two f32 into bf16x2: lo lane = x_even, hi lane = x_odd
__device__ __forceinline__ uint32_t pack_bf2(float x_even, float x_odd) {
    uint32_t r;
    asm("cvt.rn.bf16x2.f32 %0, %1, %2;" : "=r"(r) : "f"(x_odd), "f"(x_even));
    return r;
}
__device__ __forceinline__ float bf_lo(uint32_t p) { return __uint_as_float(p << 16); }
__device__ __forceinline__ float bf_hi(uint32_t p) { return __uint_as_float(p & 0xffff0000u); }

// swizzle on 16B granules within a 128B row
#define SWZ(byte_off) ((byte_off) ^ (((byte_off) >> 3) & 0x70))

// Split 8 fp32 -> bf16 hi/lo packed granule (16B each), store swizzled.
__device__ __forceinline__ void split_store_gran(char* base_hi, char* base_lo,
                                                 uint32_t byte_off, const float* v8) {
    unsigned hiw[4], low[4];
#pragma unroll
    for (int p = 0; p < 4; ++p) {
        const float x0 = v8[2 * p], x1 = v8[2 * p + 1];
        const uint32_t ph = pack_bf2(x0, x1);
        const uint32_t pl = pack_bf2(x0 - bf_lo(ph), x1 - bf_hi(ph));
        hiw[p] = ph;
        low[p] = pl;
    }
    const uint32_t so = SWZ(byte_off);
    *(uint4*)(base_hi + so) = make_uint4(hiw[0], hiw[1], hiw[2], hiw[3]);
    *(uint4*)(base_lo + so) = make_uint4(low[0], low[1], low[2], low[3]);
}

// ===========================================================================
// Kernel 1: fused QKV + gate projection (R3 scalar version, proven)
// ===========================================================================
__global__ __launch_bounds__(256) void k_gemm_qkvg(
    const float* __restrict__ A,
    const float* __restrict__ Wqkv,
    const float* __restrict__ Wg,
    const float* __restrict__ bg)
{
    __shared__ float As[16 * 132];
    __shared__ float Bs[16 * 132];
    const int tid = threadIdx.x;
    const int tx = tid & 15;
    const int ty = tid >> 4;
    const int m0 = blockIdx.y * 128;
    const int n0 = blockIdx.x * 128;

    const float* Asrc = A + (size_t)m0 * KDIM;
    const float* Bsrc = (n0 < 1536) ? (Wqkv + (size_t)n0 * KDIM)
                                    : (Wg + (size_t)(n0 - 1536) * KDIM);

    const int lr0 = tid >> 2;
    const int lk  = (tid & 3) << 2;

    float acc[8][8];
#pragma unroll
    for (int i = 0; i < 8; ++i)
#pragma unroll
        for (int j = 0; j < 8; ++j) acc[i][j] = 0.f;

    float4 a0 = *(const float4*)(Asrc + (size_t)lr0 * KDIM + lk);
    float4 a1 = *(const float4*)(Asrc + (size_t)(lr0 + 64) * KDIM + lk);
    float4 b0 = *(const float4*)(Bsrc + (size_t)lr0 * KDIM + lk);
    float4 b1 = *(const float4*)(Bsrc + (size_t)(lr0 + 64) * KDIM + lk);

    for (int kt = 0; kt < KDIM / 16; ++kt) {
        As[(lk + 0) * 132 + lr0] = a0.x;
        As[(lk + 1) * 132 + lr0] = a0.y;
        As[(lk + 2) * 132 + lr0] = a0.z;
        As[(lk + 3) * 132 + lr0] = a0.w;
        As[(lk + 0) * 132 + lr0 + 64] = a1.x;
        As[(lk + 1) * 132 + lr0 + 64] = a1.y;
        As[(lk + 2) * 132 + lr0 + 64] = a1.z;
        As[(lk + 3) * 132 + lr0 + 64] = a1.w;
        Bs[(lk + 0) * 132 + lr0] = b0.x;
        Bs[(lk + 1) * 132 + lr0] = b0.y;
        Bs[(lk + 2) * 132 + lr0] = b0.z;
        Bs[(lk + 3) * 132 + lr0] = b0.w;
        Bs[(lk + 0) * 132 + lr0 + 64] = b1.x;
        Bs[(lk + 1) * 132 + lr0 + 64] = b1.y;
        Bs[(lk + 2) * 132 + lr0 + 64] = b1.z;
        Bs[(lk + 3) * 132 + lr0 + 64] = b1.w;
        __syncthreads();

        if (kt < KDIM / 16 - 1) {
            const int kc = (kt + 1) * 16 + lk;
            a0 = *(const float4*)(Asrc + (size_t)lr0 * KDIM + kc);
            a1 = *(const float4*)(Asrc + (size_t)(lr0 + 64) * KDIM + kc);
            b0 = *(const float4*)(Bsrc + (size_t)lr0 * KDIM + kc);
            b1 = *(const float4*)(Bsrc + (size_t)(lr0 + 64) * KDIM + kc);
        }

#pragma unroll
        for (int k = 0; k < 16; ++k) {
            float4 ra0 = *(const float4*)(&As[k * 132 + ty * 4]);
            float4 ra1 = *(const float4*)(&As[k * 132 + 64 + ty * 4]);
            float4 rb0 = *(const float4*)(&Bs[k * 132 + tx * 4]);
            float4 rb1 = *(const float4*)(&Bs[k * 132 + 64 + tx * 4]);
            float af[8] = {ra0.x, ra0.y, ra0.z, ra0.w, ra1.x, ra1.y, ra1.z, ra1.w};
            float bf[8] = {rb0.x, rb0.y, rb0.z, rb0.w, rb1.x, rb1.y, rb1.z, rb1.w};
#pragma unroll
            for (int i = 0; i < 8; ++i)
#pragma unroll
                for (int j = 0; j < 8; ++j)
                    acc[i][j] = fmaf(af[i], bf[j], acc[i][j]);
        }
        __syncthreads();
    }

    const float qscale = (n0 < 512) ? 0.125f : 1.0f;
    const bool gatep = (n0 >= 1536);
#pragma unroll
    for (int i = 0; i < 8; ++i) {
        const int m = m0 + ((i < 4) ? (ty * 4 + i) : (64 + ty * 4 + (i - 4)));
#pragma unroll
        for (int jh = 0; jh < 2; ++jh) {
            const int n = n0 + jh * 64 + tx * 4;
            float v[4];
#pragma unroll
            for (int c = 0; c < 4; ++c) v[c] = acc[i][jh * 4 + c] * qscale;
            if (gatep) {
#pragma unroll
                for (int c = 0; c < 4; ++c) {
                    const float x = v[c] + bg[n - 1536 + c];
                    v[c] = 1.0f / (1.0f + __expf(-x));
                }
            }
            *(float4*)(&g_qkvg[(size_t)m * NCOLS + n]) = make_float4(v[0], v[1], v[2], v[3]);
        }
    }
}

// ===========================================================================
// Kernel 2: flash attention via mma.sync bf16x3 (hh+hl+lh emulated fp32).
// block = 64 q-rows x (head, batch); 128 threads = 4 warps x 16 rows each.
// P stays in registers (C-frag == A-frag layout). Online softmax per quad.
// ===========================================================================
#define FQT 64
#define FKT 64

__global__ __launch_bounds__(128) void k_flash_mma(const float* __restrict__ bias)
{
    __shared__ __align__(16) char sQh[8192];
    __shared__ __align__(16) char sQl[8192];
    __shared__ __align__(16) char sKh[8192];
    __shared__ __align__(16) char sKl[8192];
    __shared__ __align__(16) char sVh[8192];  // V transposed: [d][token]
    __shared__ __align__(16) char sVl[8192];

    const int tid  = threadIdx.x;
    const int warp = tid >> 5;
    const int lane = tid & 31;
    const int q0 = blockIdx.x * FQT;
    const int h  = blockIdx.y;
    const int b  = blockIdx.z;

    const size_t rbase = (size_t)b * QQ;
    const int hq = h * HD;

    const uint32_t uQh = smem_u32(sQh), uQl = smem_u32(sQl);
    const uint32_t uKh = smem_u32(sKh), uKl = smem_u32(sKl);
    const uint32_t uVh = smem_u32(sVh), uVl = smem_u32(sVl);

    // ---- Q dequant: thread owns row tid>>1, 32-col half tid&1 ----
    {
        const int r = tid >> 1, hf = tid & 1;
        const float* src = &g_qkvg[(rbase + q0 + r) * NCOLS + hq + hf * 32];
        float v[32];
#pragma unroll
        for (int g = 0; g < 8; ++g)
            *(float4*)(&v[g * 4]) = *(const float4*)(src + g * 4);
#pragma unroll
        for (int g = 0; g < 4; ++g)
            split_store_gran(sQh, sQl, (uint32_t)(r * 128 + (hf * 4 + g) * 16), &v[g * 8]);
    }
    __syncthreads();

    // ---- preload Q fragments for all 4 k-steps (hi & lo), register-resident ----
    const int lm = lane >> 3;   // ldmatrix matrix id
    const int lr = lane & 7;
    uint32_t qh[4][4], ql[4][4];
#pragma unroll
    for (int ks = 0; ks < 4; ++ks) {
        const int row = warp * 16 + ((lm & 1) ? 8 : 0) + lr;
        const int g = 2 * ks + (lm >> 1);
        const uint32_t off = SWZ((uint32_t)(row * 128 + g * 16));
        ldsm4(qh[ks], uQh + off);
        ldsm4(ql[ks], uQl + off);
    }

    const int qrow = lane >> 2;              // row within warp tile (and +8)
    const float* biasb = bias + (size_t)b * QQ * QQ;
    const float* bp0 = biasb + (size_t)(q0 + warp * 16 + qrow) * QQ + 2 * (lane & 3);
    const float* bp1 = bp0 + 8 * QQ;

    float oacc[8][4];
#pragma unroll
    for (int j = 0; j < 8; ++j)
#pragma unroll
        for (int c = 0; c < 4; ++c) oacc[j][c] = 0.f;
    float mrow0 = -3.0e38f, mrow1 = -3.0e38f, lrow0 = 0.f, lrow1 = 0.f;

    for (int kt = 0; kt < QQ / FKT; ++kt) {
        const int k0 = kt * FKT;
        __syncthreads();  // prior iteration's ldmatrix reads done

        // ---- K dequant ----
        {
            const int r = tid >> 1, hf = tid & 1;
            const float* src = &g_qkvg[(rbase + k0 + r) * NCOLS + 512 + hq + hf * 32];
            float v[32];
#pragma unroll
            for (int g = 0; g < 8; ++g)
                *(float4*)(&v[g * 4]) = *(const float4*)(src + g * 4);
#pragma unroll
            for (int g = 0; g < 4; ++g)
                split_store_gran(sKh, sKl, (uint32_t)(r * 128 + (hf * 4 + g) * 16), &v[g * 8]);
        }
        // ---- V dequant transposed: Vt[d][token] ----
        {
            const int r = tid >> 1, hf = tid & 1;
            const float* src = &g_qkvg[(rbase + k0 + r) * NCOLS + 1024 + hq + hf * 32];
            float v[32];
#pragma unroll
            for (int g = 0; g < 8; ++g)
                *(float4*)(&v[g * 4]) = *(const float4*)(src + g * 4);
#pragma unroll
            for (int c = 0; c < 32; ++c) {
                const int d = hf * 32 + c;
                const uint32_t so = SWZ((uint32_t)(d * 128 + r * 2));
                const uint32_t ph = pack_bf2(v[c], 0.f);  // lo half = value
                const float hv = bf_lo(ph);
                *(__nv_bfloat16*)(sVh + so) = __ushort_as_bfloat16((unsigned short)(ph & 0xffffu));
                const uint32_t pl = pack_bf2(v[c] - hv, 0.f);
                *(__nv_bfloat16*)(sVl + so) = __ushort_as_bfloat16((unsigned short)(pl & 0xffffu));
            }
        }
        __syncthreads();

        // ---- S = Q K^T (bf16x3) ----
        float sacc[8][4];
#pragma unroll
        for (int j = 0; j < 8; ++j)
#pragma unroll
            for (int c = 0; c < 4; ++c) sacc[j][c] = 0.f;

#pragma unroll
        for (int ks = 0; ks < 4; ++ks) {
#pragma unroll
            for (int jp = 0; jp < 4; ++jp) {
                const int tok = 16 * jp + ((lm >= 2) ? 8 : 0) + lr;
                const int g = 2 * ks + (lm & 1);
                const uint32_t off = SWZ((uint32_t)(tok * 128 + g * 16));
                uint32_t kh[4], kl[4];
                ldsm4(kh, uKh + off);
                ldsm4(kl, uKl + off);
                mma16816(sacc[2 * jp],     qh[ks], kh[0], kh[1]);
                mma16816(sacc[2 * jp + 1], qh[ks], kh[2], kh[3]);
                mma16816(sacc[2 * jp],     qh[ks], kl[0], kl[1]);
                mma16816(sacc[2 * jp + 1], qh[ks], kl[2], kl[3]);
                mma16816(sacc[2 * jp],     ql[ks], kh[0], kh[1]);
                mma16816(sacc[2 * jp + 1], ql[ks], kh[2], kh[3]);
            }
        }

        // ---- bias add ----
#pragma unroll
        for (int jt = 0; jt < 8; ++jt) {
            const float2 b0v = *(const float2*)(bp0 + k0 + 8 * jt);
            const float2 b1v = *(const float2*)(bp1 + k0 + 8 * jt);
            sacc[jt][0] += b0v.x; sacc[jt][1] += b0v.y;
            sacc[jt][2] += b1v.x; sacc[jt][3] += b1v.y;
        }

        // ---- online softmax (rows qrow and qrow+8; reduce over quad) ----
        float mx0 = sacc[0][0], mx1 = sacc[0][2];
#pragma unroll
        for (int jt = 0; jt < 8; ++jt) {
            mx0 = fmaxf(mx0, fmaxf(sacc[jt][0], sacc[jt][1]));
            mx1 = fmaxf(mx1, fmaxf(sacc[jt][2], sacc[jt][3]));
        }
        mx0 = fmaxf(mx0, __shfl_xor_sync(0xffffffffu, mx0, 1));
        mx0 = fmaxf(mx0, __shfl_xor_sync(0xffffffffu, mx0, 2));
        mx1 = fmaxf(mx1, __shfl_xor_sync(0xffffffffu, mx1, 1));
        mx1 = fmaxf(mx1, __shfl_xor_sync(0xffffffffu, mx1, 2));
        const float mn0 = fmaxf(mrow0, mx0);
        const float mn1 = fmaxf(mrow1, mx1);
        const float sc0 = __expf(mrow0 - mn0);
        const float sc1 = __expf(mrow1 - mn1);
        float ls0 = 0.f, ls1 = 0.f;
#pragma unroll
        for (int jt = 0; jt < 8; ++jt) {
            sacc[jt][0] = __expf(sacc[jt][0] - mn0);
            sacc[jt][1] = __expf(sacc[jt][1] - mn0);
            sacc[jt][2] = __expf(sacc[jt][2] - mn1);
            sacc[jt][3] = __expf(sacc[jt][3] - mn1);
            ls0 += sacc[jt][0] + sacc[jt][1];
            ls1 += sacc[jt][2] + sacc[jt][3];
        }
        ls0 += __shfl_xor_sync(0xffffffffu, ls0, 1);
        ls0 += __shfl_xor_sync(0xffffffffu, ls0, 2);
        ls1 += __shfl_xor_sync(0xffffffffu, ls1, 1);
        ls1 += __shfl_xor_sync(0xffffffffu, ls1, 2);
        lrow0 = lrow0 * sc0 + ls0;
        lrow1 = lrow1 * sc1 + ls1;
        mrow0 = mn0;
        mrow1 = mn1;
#pragma unroll
        for (int j = 0; j < 8; ++j) {
            oacc[j][0] *= sc0; oacc[j][1] *= sc0;
            oacc[j][2] *= sc1; oacc[j][3] *= sc1;
        }

        // ---- PV: O += P V (bf16x3; P register-only via C->A frag identity) ----
#pragma unroll
        for (int ks = 0; ks < 4; ++ks) {
            uint32_t ph[4], pl[4];
#pragma unroll
            for (int half = 0; half < 2; ++half) {  // a0/a1 from tile 2ks, a2/a3 from 2ks+1
                const float x0 = sacc[2 * ks + half][0], x1 = sacc[2 * ks + half][1];
                const float y0 = sacc[2 * ks + half][2], y1 = sacc[2 * ks + half][3];
                const uint32_t p0 = pack_bf2(x0, x1);
                const uint32_t p1 = pack_bf2(y0, y1);
                ph[2 * half + 0] = p0;
                ph[2 * half + 1] = p1;
                pl[2 * half + 0] = pack_bf2(x0 - bf_lo(p0), x1 - bf_hi(p0));
                pl[2 * half + 1] = pack_bf2(y0 - bf_lo(p1), y1 - bf_hi(p1));
            }
            // frag order {a0=rows0-7/k0-7, a1=rows8-15/k0-7, a2=rows0-7/k8-15, a3}
            // built above as {tile2ks c0c1, tile2ks c2c3, tile2ks+1 c0c1, tile2ks+1 c2c3}: matches.
#pragma unroll
            for (int jdp = 0; jdp < 4; ++jdp) {
                const int d = 16 * jdp + ((lm >= 2) ? 8 : 0) + lr;
                const int g = 2 * ks + (lm & 1);
                const uint32_t off = SWZ((uint32_t)(d * 128 + g * 16));
                uint32_t vh[4], vl[4];
                ldsm4(vh, uVh + off);
                ldsm4(vl, uVl + off);
                mma16816(oacc[2 * jdp],     ph, vh[0], vh[1]);
                mma16816(oacc[2 * jdp + 1], ph, vh[2], vh[3]);
                mma16816(oacc[2 * jdp],     ph, vl[0], vl[1]);
                mma16816(oacc[2 * jdp + 1], ph, vl[2], vl[3]);
                mma16816(oacc[2 * jdp],     pl, vh[0], vh[1]);
                mma16816(oacc[2 * jdp + 1], pl, vh[2], vh[3]);
            }
        }
    }

    // ---- epilogue: normalize + sigmoid gate ----
    {
        const float inv0 = 1.0f / lrow0;
        const float inv1 = 1.0f / lrow1;
        const size_t row0 = rbase + q0 + warp * 16 + qrow;
        const size_t row1 = row0 + 8;
        const int dcol = 2 * (lane & 3);
#pragma unroll
        for (int jd = 0; jd < 8; ++jd) {
            const int d = 8 * jd + dcol;
            const float2 g0 = *(const float2*)(&g_qkvg[row0 * NCOLS + 1536 + hq + d]);
            const float2 g1 = *(const float2*)(&g_qkvg[row1 * NCOLS + 1536 + hq + d]);
            float2 o0, o1;
            o0.x = oacc[jd][0] * inv0 * g0.x;
            o0.y = oacc[jd][1] * inv0 * g0.y;
            o1.x = oacc[jd][2] * inv1 * g1.x;
            o1.y = oacc[jd][3] * inv1 * g1.y;
            *(float2*)(&g_o[row0 * 512 + hq + d]) = o0;
            *(float2*)(&g_o[row1 * 512 + hq + d]) = o1;
        }
    }
}

// ===========================================================================
// Kernel 3: output projection (R3 scalar version)
// ===========================================================================
__global__ __launch_bounds__(256) void k_gemm_out(
    const float* __restrict__ Wo,
    const float* __restrict__ bo,
    float* __restrict__ out)
{
    __shared__ float As[16 * 132];
    __shared__ float Bs[16 * 132];
    const int tid = threadIdx.x;
    const int tx = tid & 15;
    const int ty = tid >> 4;
    const int m0 = blockIdx.y * 128;
    const int n0 = blockIdx.x * 128;

    const float* Asrc = g_o + (size_t)m0 * KDIM;
    const float* Bsrc = Wo + (size_t)n0 * KDIM;

    const int lr0 = tid >> 2;
    const int lk  = (tid & 3) << 2;

    float acc[8][8];
#pragma unroll
    for (int i = 0; i < 8; ++i)
#pragma unroll
        for (int j = 0; j < 8; ++j) acc[i][j] = 0.f;

    float4 a0 = *(const float4*)(Asrc + (size_t)lr0 * KDIM + lk);
    float4 a1 = *(const float4*)(Asrc + (size_t)(lr0 + 64) * KDIM + lk);
    float4 b0 = *(const float4*)(Bsrc + (size_t)lr0 * KDIM + lk);
    float4 b1 = *(const float4*)(Bsrc + (size_t)(lr0 + 64) * KDIM + lk);

    for (int kt = 0; kt < KDIM / 16; ++kt) {
        As[(lk + 0) * 132 + lr0] = a0.x;
        As[(lk + 1) * 132 + lr0] = a0.y;
        As[(lk + 2) * 132 + lr0] = a0.z;
        As[(lk + 3) * 132 + lr0] = a0.w;
        As[(lk + 0) * 132 + lr0 + 64] = a1.x;
        As[(lk + 1) * 132 + lr0 + 64] = a1.y;
        As[(lk + 2) * 132 + lr0 + 64] = a1.z;
        As[(lk + 3) * 132 + lr0 + 64] = a1.w;
        Bs[(lk + 0) * 132 + lr0] = b0.x;
        Bs[(lk + 1) * 132 + lr0] = b0.y;
        Bs[(lk + 2) * 132 + lr0] = b0.z;
        Bs[(lk + 3) * 132 + lr0] = b0.w;
        Bs[(lk + 0) * 132 + lr0 + 64] = b1.x;
        Bs[(lk + 1) * 132 + lr0 + 64] = b1.y;
        Bs[(lk + 2) * 132 + lr0 + 64] = b1.z;
        Bs[(lk + 3) * 132 + lr0 + 64] = b1.w;
        __syncthreads();

        if (kt < KDIM / 16 - 1) {
            const int kc = (kt + 1) * 16 + lk;
            a0 = *(const float4*)(Asrc + (size_t)lr0 * KDIM + kc);
            a1 = *(const float4*)(Asrc + (size_t)(lr0 + 64) * KDIM + kc);
            b0 = *(const float4*)(Bsrc + (size_t)lr0 * KDIM + kc);
            b1 = *(const float4*)(Bsrc + (size_t)(lr0 + 64) * KDIM + kc);
        }

#pragma unroll
        for (int k = 0; k < 16; ++k) {
            float4 ra0 = *(const float4*)(&As[k * 132 + ty * 4]);
            float4 ra1 = *(const float4*)(&As[k * 132 + 64 + ty * 4]);
            float4 rb0 = *(const float4*)(&Bs[k * 132 + tx * 4]);
            float4 rb1 = *(const float4*)(&Bs[k * 132 + 64 + tx * 4]);
            float af[8] = {ra0.x, ra0.y, ra0.z, ra0.w, ra1.x, ra1.y, ra1.z, ra1.w};
            float bf[8] = {rb0.x, rb0.y, rb0.z, rb0.w, rb1.x, rb1.y, rb1.z, rb1.w};
#pragma unroll
            for (int i = 0; i < 8; ++i)
#pragma unroll
                for (int j = 0; j < 8; ++j)
                    acc[i][j] = fmaf(af[i], bf[j], acc[i][j]);
        }
        __syncthreads();
    }

#pragma unroll
    for (int i = 0; i < 8; ++i) {
        const int m = m0 + ((i < 4) ? (ty * 4 + i) : (64 + ty * 4 + (i - 4)));
#pragma unroll
        for (int jh = 0; jh < 2; ++jh) {
            const int n = n0 + jh * 64 + tx * 4;
            float4 o4;
            o4.x = acc[i][jh * 4 + 0] + bo[n + 0];
            o4.y = acc[i][jh * 4 + 1] + bo[n + 1];
            o4.z = acc[i][jh * 4 + 2] + bo[n + 2];
            o4.w = acc[i][jh * 4 + 3] + bo[n + 3];
            *(float4*)(&out[(size_t)m * 512 + n]) = o4;
        }
    }
}

// ---------------------------------------------------------------------------
extern "C" void kernel_launch(void* const* d_in, const int* in_sizes, int n_in,
                              void* d_out, int out_size)
{
    (void)in_sizes; (void)n_in; (void)out_size;
    const float* q_x   = (const float*)d_in[0];
    // d_in[1] = kv_x (unused by the reference)
    const float* bias  = (const float*)d_in[2];
    const float* w_qkv = (const float*)d_in[3];
    const float* w_o   = (const float*)d_in[4];
    const float* b_o   = (const float*)d_in[5];
    const float* w_g   = (const float*)d_in[6];
    const float* b_g   = (const float*)d_in[7];
    float* out = (float*)d_out;

    dim3 g1(NCOLS / 128, MROWS / 128);  // (16, 32)
    k_gemm_qkvg<<<g1, 256>>>(q_x, w_qkv, w_g, b_g);

    dim3 g2(QQ / FQT, NH, BB);          // (32, 8, 2)
    k_flash_mma<<<g2, 128>>>(bias);

    dim3 g3(512 / 128, MROWS / 128);    // (4, 32)
    k_gemm_out<<<g3, 256>>>(w_o, b_o, out);
}

// round 13
// speedup vs baseline: 1.7067x; 1.1645x over previous
#include <cuda_runtime.h>
#include <cuda_bf16.h>
#include <math.h>
#include <stdint.h>

// Problem dims (fixed)
#define BB 2
#define QQ 2048
#define CQd 512
#define NH 8
#define HD 64
#define MROWS (BB * QQ)   // 4096
#define NCOLS 2048        // 3*H*D (qkv) + H*D (gate)
#define KDIM 512

// Scratch (no allocations allowed -> device globals)
__device__ float g_qkvg[(size_t)MROWS * NCOLS];          // v (fp32) | gate (fp32); q/k slots unused now
__device__ float g_o[(size_t)MROWS * 512];               // gated attention output
__device__ __nv_bfloat16 g_qhi[(size_t)MROWS * 512];     // Q split-bf16 (scaled by 1/8)
__device__ __nv_bfloat16 g_qlo[(size_t)MROWS * 512];
__device__ __nv_bfloat16 g_khi[(size_t)MROWS * 512];     // K split-bf16
__device__ __nv_bfloat16 g_klo[(size_t)MROWS * 512];
__device__ __nv_bfloat16 g_vthi[(size_t)BB * NH * HD * QQ]; // V^T split-bf16: [b][h][d][token]
__device__ __nv_bfloat16 g_vtlo[(size_t)BB * NH * HD * QQ];

// ===========================================================================
// Baseline-PTX tensor helpers (sm_80-era: valid on compute_103 base target)
// ===========================================================================
__device__ __forceinline__ uint32_t smem_u32(const void* p) {
    uint32_t a;
    asm("{ .reg .u64 t; cvta.to.shared.u64 t, %1; cvt.u32.u64 %0, t; }"
        : "=r"(a) : "l"(p));
    return a;
}

__device__ __forceinline__ void ldsm4(uint32_t* r, uint32_t addr) {
    asm volatile("ldmatrix.sync.aligned.m8n8.x4.shared.b16 {%0,%1,%2,%3}, [%4];"
                 : "=r"(r[0]), "=r"(r[1]), "=r"(r[2]), "=r"(r[3]) : "r"(addr));
}

__device__ __forceinline__ void mma16816(float* c, const uint32_t* a,
                                         uint32_t b0, uint32_t b1) {
    asm volatile(
        "mma.sync.aligned.m16n8k16.row.col.f32.bf16.bf16.f32 "
        "{%0,%1,%2,%3}, {%4,%5,%6,%7}, {%8,%9}, {%0,%1,%2,%3};"
        : "+f"(c[0]), "+f"(c[1]), "+f"(c[2]), "+f"(c[3])
        : "r"(a[0]), "r"(a[1]), "r"(a[2]), "r"(a[3]), "r"(b0), "r"(b1));
}

// pack two f32 into bf16x2: lo half = x_even, hi half = x_odd
__device__ __forceinline__ uint32_t pack_bf2(float x_even, float x_odd) {
    uint32_t r;
    asm("cvt.rn.bf16x2.f32 %0, %1, %2;" : "=r"(r) : "f"(x_odd), "f"(x_even));
    return r;
}
__device__ __forceinline__ float bf_lo(uint32_t p) { return __uint_as_float(p << 16); }
__device__ __forceinline__ float bf_hi(uint32_t p) { return __uint_as_float(p & 0xffff0000u); }

// swizzle on 16B granules within a 128B row
#define SWZ(byte_off) ((byte_off) ^ (((byte_off) >> 3) & 0x70))

// ===========================================================================
// Kernel 1: fused QKV + gate projection.
// Epilogue: q -> scaled split-bf16 (g_qhi/g_qlo); k -> split-bf16 (g_khi/g_klo);
//           v -> fp32 g_qkvg; gate -> sigmoid fp32 g_qkvg.
// ===========================================================================
__global__ __launch_bounds__(256) void k_gemm_qkvg(
    const float* __restrict__ A,
    const float* __restrict__ Wqkv,
    const float* __restrict__ Wg,
    const float* __restrict__ bg)
{
    __shared__ float As[16 * 132];
    __shared__ float Bs[16 * 132];
    const int tid = threadIdx.x;
    const int tx = tid & 15;
    const int ty = tid >> 4;
    const int m0 = blockIdx.y * 128;
    const int n0 = blockIdx.x * 128;

    const float* Asrc = A + (size_t)m0 * KDIM;
    const float* Bsrc = (n0 < 1536) ? (Wqkv + (size_t)n0 * KDIM)
                                    : (Wg + (size_t)(n0 - 1536) * KDIM);

    const int lr0 = tid >> 2;
    const int lk  = (tid & 3) << 2;

    float acc[8][8];
#pragma unroll
    for (int i = 0; i < 8; ++i)
#pragma unroll
        for (int j = 0; j < 8; ++j) acc[i][j] = 0.f;

    float4 a0 = *(const float4*)(Asrc + (size_t)lr0 * KDIM + lk);
    float4 a1 = *(const float4*)(Asrc + (size_t)(lr0 + 64) * KDIM + lk);
    float4 b0 = *(const float4*)(Bsrc + (size_t)lr0 * KDIM + lk);
    float4 b1 = *(const float4*)(Bsrc + (size_t)(lr0 + 64) * KDIM + lk);

    for (int kt = 0; kt < KDIM / 16; ++kt) {
        As[(lk + 0) * 132 + lr0] = a0.x;
        As[(lk + 1) * 132 + lr0] = a0.y;
        As[(lk + 2) * 132 + lr0] = a0.z;
        As[(lk + 3) * 132 + lr0] = a0.w;
        As[(lk + 0) * 132 + lr0 + 64] = a1.x;
        As[(lk + 1) * 132 + lr0 + 64] = a1.y;
        As[(lk + 2) * 132 + lr0 + 64] = a1.z;
        As[(lk + 3) * 132 + lr0 + 64] = a1.w;
        Bs[(lk + 0) * 132 + lr0] = b0.x;
        Bs[(lk + 1) * 132 + lr0] = b0.y;
        Bs[(lk + 2) * 132 + lr0] = b0.z;
        Bs[(lk + 3) * 132 + lr0] = b0.w;
        Bs[(lk + 0) * 132 + lr0 + 64] = b1.x;
        Bs[(lk + 1) * 132 + lr0 + 64] = b1.y;
        Bs[(lk + 2) * 132 + lr0 + 64] = b1.z;
        Bs[(lk + 3) * 132 + lr0 + 64] = b1.w;
        __syncthreads();

        if (kt < KDIM / 16 - 1) {
            const int kc = (kt + 1) * 16 + lk;
            a0 = *(const float4*)(Asrc + (size_t)lr0 * KDIM + kc);
            a1 = *(const float4*)(Asrc + (size_t)(lr0 + 64) * KDIM + kc);
            b0 = *(const float4*)(Bsrc + (size_t)lr0 * KDIM + kc);
            b1 = *(const float4*)(Bsrc + (size_t)(lr0 + 64) * KDIM + kc);
        }

#pragma unroll
        for (int k = 0; k < 16; ++k) {
            float4 ra0 = *(const float4*)(&As[k * 132 + ty * 4]);
            float4 ra1 = *(const float4*)(&As[k * 132 + 64 + ty * 4]);
            float4 rb0 = *(const float4*)(&Bs[k * 132 + tx * 4]);
            float4 rb1 = *(const float4*)(&Bs[k * 132 + 64 + tx * 4]);
            float af[8] = {ra0.x, ra0.y, ra0.z, ra0.w, ra1.x, ra1.y, ra1.z, ra1.w};
            float bf[8] = {rb0.x, rb0.y, rb0.z, rb0.w, rb1.x, rb1.y, rb1.z, rb1.w};
#pragma unroll
            for (int i = 0; i < 8; ++i)
#pragma unroll
                for (int j = 0; j < 8; ++j)
                    acc[i][j] = fmaf(af[i], bf[j], acc[i][j]);
        }
        __syncthreads();
    }

    const int region = n0 >> 9;   // 0=q, 1=k, 2=v, 3=gate
    const float qscale = (region == 0) ? 0.125f : 1.0f;
#pragma unroll
    for (int i = 0; i < 8; ++i) {
        const int m = m0 + ((i < 4) ? (ty * 4 + i) : (64 + ty * 4 + (i - 4)));
#pragma unroll
        for (int jh = 0; jh < 2; ++jh) {
            const int n = n0 + jh * 64 + tx * 4;
            float v[4];
#pragma unroll
            for (int c = 0; c < 4; ++c) v[c] = acc[i][jh * 4 + c] * qscale;
            if (region <= 1) {
                // split-bf16 store to q or k buffers
                uint2 hiw, low;
                hiw.x = pack_bf2(v[0], v[1]);
                hiw.y = pack_bf2(v[2], v[3]);
                low.x = pack_bf2(v[0] - bf_lo(hiw.x), v[1] - bf_hi(hiw.x));
                low.y = pack_bf2(v[2] - bf_lo(hiw.y), v[3] - bf_hi(hiw.y));
                const size_t idx = (size_t)m * 512 + (n - region * 512);
                if (region == 0) {
                    *(uint2*)(&g_qhi[idx]) = hiw;
                    *(uint2*)(&g_qlo[idx]) = low;
                } else {
                    *(uint2*)(&g_khi[idx]) = hiw;
                    *(uint2*)(&g_klo[idx]) = low;
                }
            } else {
                if (region == 3) {
#pragma unroll
                    for (int c = 0; c < 4; ++c) {
                        const float x = v[c] + bg[n - 1536 + c];
                        v[c] = 1.0f / (1.0f + __expf(-x));
                    }
                }
                *(float4*)(&g_qkvg[(size_t)m * NCOLS + n]) =
                    make_float4(v[0], v[1], v[2], v[3]);
            }
        }
    }
}

// ===========================================================================
// Kernel 1b: V transpose + bf16 hi/lo split.  [token][d] fp32 -> [b,h][d][token] bf16
// grid (16 token-chunks, 8 heads, 2 batch), 256 threads.
// ===========================================================================
__global__ __launch_bounds__(256) void k_vsplit()
{
    __shared__ float t[128][65];
    const int tid = threadIdx.x;
    const int tok0 = blockIdx.x * 128;
    const int h = blockIdx.y;
    const int b = blockIdx.z;
    const size_t rbase = (size_t)b * QQ;

    // read [128 tok][64 d] fp32
#pragma unroll
    for (int i = 0; i < 8; ++i) {
        const int a = tid + i * 256;        // 0..2047 float4s
        const int r = a >> 4;
        const int c = (a & 15) * 4;
        const float4 v = *(const float4*)(&g_qkvg[(rbase + tok0 + r) * NCOLS + 1024 + h * HD + c]);
        t[r][c + 0] = v.x; t[r][c + 1] = v.y; t[r][c + 2] = v.z; t[r][c + 3] = v.w;
    }
    __syncthreads();

    // write transposed: thread owns d = tid>>2, tokens (tid&3)*32 .. +32
    const int d = tid >> 2;
    const int tq = (tid & 3) * 32;
    uint32_t hiw[16], low[16];
#pragma unroll
    for (int j = 0; j < 16; ++j) {
        const float x0 = t[tq + 2 * j][d];
        const float x1 = t[tq + 2 * j + 1][d];
        const uint32_t ph = pack_bf2(x0, x1);
        hiw[j] = ph;
        low[j] = pack_bf2(x0 - bf_lo(ph), x1 - bf_hi(ph));
    }
    const size_t dst = ((size_t)(b * NH + h) * HD + d) * QQ + tok0 + tq;
#pragma unroll
    for (int j = 0; j < 4; ++j) {
        *(uint4*)(&g_vthi[dst + j * 8]) = make_uint4(hiw[4*j], hiw[4*j+1], hiw[4*j+2], hiw[4*j+3]);
        *(uint4*)(&g_vtlo[dst + j * 8]) = make_uint4(low[4*j], low[4*j+1], low[4*j+2], low[4*j+3]);
    }
}

// ===========================================================================
// Kernel 2: flash attention via mma.sync bf16x3 (hh+hl+lh emulated fp32).
// block = 128 q-rows x (head, batch); 256 threads = 8 warps x 16 rows each.
// K/V/Q arrive pre-split in bf16 -> smem fill is pure float4 copies.
// ===========================================================================
#define FQT 128
#define FKT 64

// dynamic smem offsets
#define FO_QH 0
#define FO_QL 16384
#define FO_KH 32768
#define FO_KL 40960
#define FO_VH 49152
#define FO_VL 57344
#define FO_TOTAL 65536

__global__ __launch_bounds__(256) void k_flash_mma(const float* __restrict__ bias)
{
    extern __shared__ __align__(16) char smem[];
    char* sQh = smem + FO_QH;
    char* sQl = smem + FO_QL;
    char* sKh = smem + FO_KH;
    char* sKl = smem + FO_KL;
    char* sVh = smem + FO_VH;
    char* sVl = smem + FO_VL;

    const int tid  = threadIdx.x;
    const int warp = tid >> 5;
    const int lane = tid & 31;
    const int q0 = blockIdx.x * FQT;
    const int h  = blockIdx.y;
    const int b  = blockIdx.z;

    const size_t rbase = (size_t)b * QQ;
    const int hq = h * HD;

    const uint32_t uQh = smem_u32(sQh), uQl = smem_u32(sQl);
    const uint32_t uKh = smem_u32(sKh), uKl = smem_u32(sKl);
    const uint32_t uVh = smem_u32(sVh), uVl = smem_u32(sVl);

    // ---- Q copy: 1024 granules (16B) per buffer, 4 per thread ----
#pragma unroll
    for (int i = 0; i < 4; ++i) {
        const int a = tid + i * 256;
        const int r = a >> 3;
        const int g = a & 7;
        const size_t src = (rbase + q0 + r) * 512 + hq + g * 8;
        const uint32_t so = SWZ((uint32_t)(r * 128 + g * 16));
        *(uint4*)(sQh + so) = *(const uint4*)(&g_qhi[src]);
        *(uint4*)(sQl + so) = *(const uint4*)(&g_qlo[src]);
    }
    __syncthreads();

    // ---- preload Q fragments for all 4 k-steps (hi & lo), register-resident ----
    const int lm = lane >> 3;   // ldmatrix matrix id
    const int lr = lane & 7;
    uint32_t qh[4][4], ql[4][4];
#pragma unroll
    for (int ks = 0; ks < 4; ++ks) {
        const int row = warp * 16 + ((lm & 1) ? 8 : 0) + lr;
        const int g = 2 * ks + (lm >> 1);
        const uint32_t off = SWZ((uint32_t)(row * 128 + g * 16));
        ldsm4(qh[ks], uQh + off);
        ldsm4(ql[ks], uQl + off);
    }

    const int qrow = lane >> 2;              // row within warp tile (and +8)
    const float* biasb = bias + (size_t)b * QQ * QQ;
    const float* bp0 = biasb + (size_t)(q0 + warp * 16 + qrow) * QQ + 2 * (lane & 3);
    const float* bp1 = bp0 + 8 * QQ;

    const size_t vtb = (size_t)(b * NH + h) * HD;  // base d-row index into g_vthi

    float oacc[8][4];
#pragma unroll
    for (int j = 0; j < 8; ++j)
#pragma unroll
        for (int c = 0; c < 4; ++c) oacc[j][c] = 0.f;
    float mrow0 = -3.0e38f, mrow1 = -3.0e38f, lrow0 = 0.f, lrow1 = 0.f;

    for (int kt = 0; kt < QQ / FKT; ++kt) {
        const int k0 = kt * FKT;
        __syncthreads();  // prior iteration's ldmatrix reads done

        // ---- K copy: 512 granules per buffer, 2 per thread ----
#pragma unroll
        for (int i = 0; i < 2; ++i) {
            const int a = tid + i * 256;
            const int r = a >> 3;
            const int g = a & 7;
            const size_t src = (rbase + k0 + r) * 512 + hq + g * 8;
            const uint32_t so = SWZ((uint32_t)(r * 128 + g * 16));
            *(uint4*)(sKh + so) = *(const uint4*)(&g_khi[src]);
            *(uint4*)(sKl + so) = *(const uint4*)(&g_klo[src]);
        }
        // ---- V^T copy: 512 granules per buffer, 2 per thread ----
#pragma unroll
        for (int i = 0; i < 2; ++i) {
            const int a = tid + i * 256;
            const int d = a >> 3;
            const int g = a & 7;           // granule of 8 tokens
            const size_t src = (vtb + d) * QQ + k0 + g * 8;
            const uint32_t so = SWZ((uint32_t)(d * 128 + g * 16));
            *(uint4*)(sVh + so) = *(const uint4*)(&g_vthi[src]);
            *(uint4*)(sVl + so) = *(const uint4*)(&g_vtlo[src]);
        }
        __syncthreads();

        // ---- S = Q K^T (bf16x3) ----
        float sacc[8][4];
#pragma unroll
        for (int j = 0; j < 8; ++j)
#pragma unroll
            for (int c = 0; c < 4; ++c) sacc[j][c] = 0.f;

#pragma unroll
        for (int ks = 0; ks < 4; ++ks) {
#pragma unroll
            for (int jp = 0; jp < 4; ++jp) {
                const int tok = 16 * jp + ((lm >= 2) ? 8 : 0) + lr;
                const int g = 2 * ks + (lm & 1);
                const uint32_t off = SWZ((uint32_t)(tok * 128 + g * 16));
                uint32_t kh[4], kl[4];
                ldsm4(kh, uKh + off);
                ldsm4(kl, uKl + off);
                mma16816(sacc[2 * jp],     qh[ks], kh[0], kh[1]);
                mma16816(sacc[2 * jp + 1], qh[ks], kh[2], kh[3]);
                mma16816(sacc[2 * jp],     qh[ks], kl[0], kl[1]);
                mma16816(sacc[2 * jp + 1], qh[ks], kl[2], kl[3]);
                mma16816(sacc[2 * jp],     ql[ks], kh[0], kh[1]);
                mma16816(sacc[2 * jp + 1], ql[ks], kh[2], kh[3]);
            }
        }

        // ---- bias add ----
#pragma unroll
        for (int jt = 0; jt < 8; ++jt) {
            const float2 b0v = *(const float2*)(bp0 + k0 + 8 * jt);
            const float2 b1v = *(const float2*)(bp1 + k0 + 8 * jt);
            sacc[jt][0] += b0v.x; sacc[jt][1] += b0v.y;
            sacc[jt][2] += b1v.x; sacc[jt][3] += b1v.y;
        }

        // ---- online softmax (rows qrow and qrow+8; reduce over quad) ----
        float mx0 = sacc[0][0], mx1 = sacc[0][2];
#pragma unroll
        for (int jt = 0; jt < 8; ++jt) {
            mx0 = fmaxf(mx0, fmaxf(sacc[jt][0], sacc[jt][1]));
            mx1 = fmaxf(mx1, fmaxf(sacc[jt][2], sacc[jt][3]));
        }
        mx0 = fmaxf(mx0, __shfl_xor_sync(0xffffffffu, mx0, 1));
        mx0 = fmaxf(mx0, __shfl_xor_sync(0xffffffffu, mx0, 2));
        mx1 = fmaxf(mx1, __shfl_xor_sync(0xffffffffu, mx1, 1));
        mx1 = fmaxf(mx1, __shfl_xor_sync(0xffffffffu, mx1, 2));
        const float mn0 = fmaxf(mrow0, mx0);
        const float mn1 = fmaxf(mrow1, mx1);
        const float sc0 = __expf(mrow0 - mn0);
        const float sc1 = __expf(mrow1 - mn1);
        float ls0 = 0.f, ls1 = 0.f;
#pragma unroll
        for (int jt = 0; jt < 8; ++jt) {
            sacc[jt][0] = __expf(sacc[jt][0] - mn0);
            sacc[jt][1] = __expf(sacc[jt][1] - mn0);
            sacc[jt][2] = __expf(sacc[jt][2] - mn1);
            sacc[jt][3] = __expf(sacc[jt][3] - mn1);
            ls0 += sacc[jt][0] + sacc[jt][1];
            ls1 += sacc[jt][2] + sacc[jt][3];
        }
        ls0 += __shfl_xor_sync(0xffffffffu, ls0, 1);
        ls0 += __shfl_xor_sync(0xffffffffu, ls0, 2);
        ls1 += __shfl_xor_sync(0xffffffffu, ls1, 1);
        ls1 += __shfl_xor_sync(0xffffffffu, ls1, 2);
        lrow0 = lrow0 * sc0 + ls0;
        lrow1 = lrow1 * sc1 + ls1;
        mrow0 = mn0;
        mrow1 = mn1;
#pragma unroll
        for (int j = 0; j < 8; ++j) {
            oacc[j][0] *= sc0; oacc[j][1] *= sc0;
            oacc[j][2] *= sc1; oacc[j][3] *= sc1;
        }

        // ---- PV: O += P V (bf16x3; P register-only via C->A frag identity) ----
#pragma unroll
        for (int ks = 0; ks < 4; ++ks) {
            uint32_t ph[4], pl[4];
#pragma unroll
            for (int half = 0; half < 2; ++half) {
                const float x0 = sacc[2 * ks + half][0], x1 = sacc[2 * ks + half][1];
                const float y0 = sacc[2 * ks + half][2], y1 = sacc[2 * ks + half][3];
                const uint32_t p0 = pack_bf2(x0, x1);
                const uint32_t p1 = pack_bf2(y0, y1);
                ph[2 * half + 0] = p0;
                ph[2 * half + 1] = p1;
                pl[2 * half + 0] = pack_bf2(x0 - bf_lo(p0), x1 - bf_hi(p0));
                pl[2 * half + 1] = pack_bf2(y0 - bf_lo(p1), y1 - bf_hi(p1));
            }
#pragma unroll
            for (int jdp = 0; jdp < 4; ++jdp) {
                const int d = 16 * jdp + ((lm >= 2) ? 8 : 0) + lr;
                const int g = 2 * ks + (lm & 1);
                const uint32_t off = SWZ((uint32_t)(d * 128 + g * 16));
                uint32_t vh[4], vl[4];
                ldsm4(vh, uVh + off);
                ldsm4(vl, uVl + off);
                mma16816(oacc[2 * jdp],     ph, vh[0], vh[1]);
                mma16816(oacc[2 * jdp + 1], ph, vh[2], vh[3]);
                mma16816(oacc[2 * jdp],     ph, vl[0], vl[1]);
                mma16816(oacc[2 * jdp + 1], ph, vl[2], vl[3]);
                mma16816(oacc[2 * jdp],     pl, vh[0], vh[1]);
                mma16816(oacc[2 * jdp + 1], pl, vh[2], vh[3]);
            }
        }
    }

    // ---- epilogue: normalize + sigmoid gate ----
    {
        const float inv0 = 1.0f / lrow0;
        const float inv1 = 1.0f / lrow1;
        const size_t row0 = rbase + q0 + warp * 16 + qrow;
        const size_t row1 = row0 + 8;
        const int dcol = 2 * (lane & 3);
#pragma unroll
        for (int jd = 0; jd < 8; ++jd) {
            const int d = 8 * jd + dcol;
            const float2 g0 = *(const float2*)(&g_qkvg[row0 * NCOLS + 1536 + hq + d]);
            const float2 g1 = *(const float2*)(&g_qkvg[row1 * NCOLS + 1536 + hq + d]);
            float2 o0, o1;
            o0.x = oacc[jd][0] * inv0 * g0.x;
            o0.y = oacc[jd][1] * inv0 * g0.y;
            o1.x = oacc[jd][2] * inv1 * g1.x;
            o1.y = oacc[jd][3] * inv1 * g1.y;
            *(float2*)(&g_o[row0 * 512 + hq + d]) = o0;
            *(float2*)(&g_o[row1 * 512 + hq + d]) = o1;
        }
    }
}

// ===========================================================================
// Kernel 3: output projection (R3 scalar version)
// ===========================================================================
__global__ __launch_bounds__(256) void k_gemm_out(
    const float* __restrict__ Wo,
    const float* __restrict__ bo,
    float* __restrict__ out)
{
    __shared__ float As[16 * 132];
    __shared__ float Bs[16 * 132];
    const int tid = threadIdx.x;
    const int tx = tid & 15;
    const int ty = tid >> 4;
    const int m0 = blockIdx.y * 128;
    const int n0 = blockIdx.x * 128;

    const float* Asrc = g_o + (size_t)m0 * KDIM;
    const float* Bsrc = Wo + (size_t)n0 * KDIM;

    const int lr0 = tid >> 2;
    const int lk  = (tid & 3) << 2;

    float acc[8][8];
#pragma unroll
    for (int i = 0; i < 8; ++i)
#pragma unroll
        for (int j = 0; j < 8; ++j) acc[i][j] = 0.f;

    float4 a0 = *(const float4*)(Asrc + (size_t)lr0 * KDIM + lk);
    float4 a1 = *(const float4*)(Asrc + (size_t)(lr0 + 64) * KDIM + lk);
    float4 b0 = *(const float4*)(Bsrc + (size_t)lr0 * KDIM + lk);
    float4 b1 = *(const float4*)(Bsrc + (size_t)(lr0 + 64) * KDIM + lk);

    for (int kt = 0; kt < KDIM / 16; ++kt) {
        As[(lk + 0) * 132 + lr0] = a0.x;
        As[(lk + 1) * 132 + lr0] = a0.y;
        As[(lk + 2) * 132 + lr0] = a0.z;
        As[(lk + 3) * 132 + lr0] = a0.w;
        As[(lk + 0) * 132 + lr0 + 64] = a1.x;
        As[(lk + 1) * 132 + lr0 + 64] = a1.y;
        As[(lk + 2) * 132 + lr0 + 64] = a1.z;
        As[(lk + 3) * 132 + lr0 + 64] = a1.w;
        Bs[(lk + 0) * 132 + lr0] = b0.x;
        Bs[(lk + 1) * 132 + lr0] = b0.y;
        Bs[(lk + 2) * 132 + lr0] = b0.z;
        Bs[(lk + 3) * 132 + lr0] = b0.w;
        Bs[(lk + 0) * 132 + lr0 + 64] = b1.x;
        Bs[(lk + 1) * 132 + lr0 + 64] = b1.y;
        Bs[(lk + 2) * 132 + lr0 + 64] = b1.z;
        Bs[(lk + 3) * 132 + lr0 + 64] = b1.w;
        __syncthreads();

        if (kt < KDIM / 16 - 1) {
            const int kc = (kt + 1) * 16 + lk;
            a0 = *(const float4*)(Asrc + (size_t)lr0 * KDIM + kc);
            a1 = *(const float4*)(Asrc + (size_t)(lr0 + 64) * KDIM + kc);
            b0 = *(const float4*)(Bsrc + (size_t)lr0 * KDIM + kc);
            b1 = *(const float4*)(Bsrc + (size_t)(lr0 + 64) * KDIM + kc);
        }

#pragma unroll
        for (int k = 0; k < 16; ++k) {
            float4 ra0 = *(const float4*)(&As[k * 132 + ty * 4]);
            float4 ra1 = *(const float4*)(&As[k * 132 + 64 + ty * 4]);
            float4 rb0 = *(const float4*)(&Bs[k * 132 + tx * 4]);
            float4 rb1 = *(const float4*)(&Bs[k * 132 + 64 + tx * 4]);
            float af[8] = {ra0.x, ra0.y, ra0.z, ra0.w, ra1.x, ra1.y, ra1.z, ra1.w};
            float bf[8] = {rb0.x, rb0.y, rb0.z, rb0.w, rb1.x, rb1.y, rb1.z, rb1.w};
#pragma unroll
            for (int i = 0; i < 8; ++i)
#pragma unroll
                for (int j = 0; j < 8; ++j)
                    acc[i][j] = fmaf(af[i], bf[j], acc[i][j]);
        }
        __syncthreads();
    }

#pragma unroll
    for (int i = 0; i < 8; ++i) {
        const int m = m0 + ((i < 4) ? (ty * 4 + i) : (64 + ty * 4 + (i - 4)));
#pragma unroll
        for (int jh = 0; jh < 2; ++jh) {
            const int n = n0 + jh * 64 + tx * 4;
            float4 o4;
            o4.x = acc[i][jh * 4 + 0] + bo[n + 0];
            o4.y = acc[i][jh * 4 + 1] + bo[n + 1];
            o4.z = acc[i][jh * 4 + 2] + bo[n + 2];
            o4.w = acc[i][jh * 4 + 3] + bo[n + 3];
            *(float4*)(&out[(size_t)m * 512 + n]) = o4;
        }
    }
}

// ---------------------------------------------------------------------------
extern "C" void kernel_launch(void* const* d_in, const int* in_sizes, int n_in,
                              void* d_out, int out_size)
{
    (void)in_sizes; (void)n_in; (void)out_size;
    const float* q_x   = (const float*)d_in[0];
    // d_in[1] = kv_x (unused by the reference)
    const float* bias  = (const float*)d_in[2];
    const float* w_qkv = (const float*)d_in[3];
    const float* w_o   = (const float*)d_in[4];
    const float* b_o   = (const float*)d_in[5];
    const float* w_g   = (const float*)d_in[6];
    const float* b_g   = (const float*)d_in[7];
    float* out = (float*)d_out;

    cudaFuncSetAttribute(k_flash_mma, cudaFuncAttributeMaxDynamicSharedMemorySize,
                         (int)FO_TOTAL);

    dim3 g1(NCOLS / 128, MROWS / 128);  // (16, 32)
    k_gemm_qkvg<<<g1, 256>>>(q_x, w_qkv, w_g, b_g);

    dim3 gv(QQ / 128, NH, BB);          // (16, 8, 2)
    k_vsplit<<<gv, 256>>>();

    dim3 g2(QQ / FQT, NH, BB);          // (16, 8, 2)
    k_flash_mma<<<g2, 256, FO_TOTAL>>>(bias);

    dim3 g3(512 / 128, MROWS / 128);    // (4, 32)
    k_gemm_out<<<g3, 256>>>(w_o, b_o, out);
}

// round 14
// speedup vs baseline: 2.2034x; 1.2910x over previous
#include <cuda_runtime.h>
#include <cuda_bf16.h>
#include <math.h>
#include <stdint.h>

// Problem dims (fixed)
#define BB 2
#define QQ 2048
#define CQd 512
#define NH 8
#define HD 64
#define MROWS (BB * QQ)   // 4096
#define NCOLS 2048        // layout inside g_qkvg: [q|k|v|gate] (q/k slots unused now)
#define KDIM 512

// Scratch (no allocations allowed -> device globals)
__device__ float g_qkvg[(size_t)MROWS * NCOLS];          // v (fp32) | gate (fp32)
__device__ __nv_bfloat16 g_ahi[(size_t)MROWS * 512];     // q_x split
__device__ __nv_bfloat16 g_alo[(size_t)MROWS * 512];
__device__ __nv_bfloat16 g_bhi[(size_t)2048 * 512];      // [w_qkv; w_g] split
__device__ __nv_bfloat16 g_blo[(size_t)2048 * 512];
__device__ __nv_bfloat16 g_wohi[(size_t)512 * 512];      // w_o split
__device__ __nv_bfloat16 g_wolo[(size_t)512 * 512];
__device__ __nv_bfloat16 g_qhi[(size_t)MROWS * 512];     // Q split (scaled by 1/8)
__device__ __nv_bfloat16 g_qlo[(size_t)MROWS * 512];
__device__ __nv_bfloat16 g_khi[(size_t)MROWS * 512];     // K split
__device__ __nv_bfloat16 g_klo[(size_t)MROWS * 512];
__device__ __nv_bfloat16 g_vthi[(size_t)BB * NH * HD * QQ]; // V^T split: [b][h][d][token]
__device__ __nv_bfloat16 g_vtlo[(size_t)BB * NH * HD * QQ];
__device__ __nv_bfloat16 g_ohi[(size_t)MROWS * 512];     // gated attention out, split
__device__ __nv_bfloat16 g_olo[(size_t)MROWS * 512];

// ===========================================================================
// Baseline-PTX tensor helpers (sm_80-era: valid on compute_103 base target)
// ===========================================================================
__device__ __forceinline__ uint32_t smem_u32(const void* p) {
    uint32_t a;
    asm("{ .reg .u64 t; cvta.to.shared.u64 t, %1; cvt.u32.u64 %0, t; }"
        : "=r"(a) : "l"(p));
    return a;
}

__device__ __forceinline__ void ldsm4(uint32_t* r, uint32_t addr) {
    asm volatile("ldmatrix.sync.aligned.m8n8.x4.shared.b16 {%0,%1,%2,%3}, [%4];"
                 : "=r"(r[0]), "=r"(r[1]), "=r"(r[2]), "=r"(r[3]) : "r"(addr));
}

__device__ __forceinline__ void mma16816(float* c, const uint32_t* a,
                                         uint32_t b0, uint32_t b1) {
    asm volatile(
        "mma.sync.aligned.m16n8k16.row.col.f32.bf16.bf16.f32 "
        "{%0,%1,%2,%3}, {%4,%5,%6,%7}, {%8,%9}, {%0,%1,%2,%3};"
        : "+f"(c[0]), "+f"(c[1]), "+f"(c[2]), "+f"(c[3])
        : "r"(a[0]), "r"(a[1]), "r"(a[2]), "r"(a[3]), "r"(b0), "r"(b1));
}

// pack two f32 into bf16x2: lo half = x_even, hi half = x_odd
__device__ __forceinline__ uint32_t pack_bf2(float x_even, float x_odd) {
    uint32_t r;
    asm("cvt.rn.bf16x2.f32 %0, %1, %2;" : "=r"(r) : "f"(x_odd), "f"(x_even));
    return r;
}
__device__ __forceinline__ float bf_lo(uint32_t p) { return __uint_as_float(p << 16); }
__device__ __forceinline__ float bf_hi(uint32_t p) { return __uint_as_float(p & 0xffff0000u); }

// swizzle on 16B granules within a 128B row
#define SWZ(byte_off) ((byte_off) ^ (((byte_off) >> 3) & 0x70))

// ===========================================================================
// Split kernel: fp32 -> bf16 hi/lo. One float4 per thread.
// which: 0=q_x->A, 1=w_qkv->B[0:1536], 2=w_g->B[1536:2048], 3=w_o->WO
// ===========================================================================
__global__ __launch_bounds__(256) void k_split(const float* __restrict__ src, int which)
{
    const size_t i = (size_t)blockIdx.x * 256 + threadIdx.x;  // float4 index
    const float4 v = *(const float4*)(src + i * 4);
    uint2 hiw, low;
    hiw.x = pack_bf2(v.x, v.y);
    hiw.y = pack_bf2(v.z, v.w);
    low.x = pack_bf2(v.x - bf_lo(hiw.x), v.y - bf_hi(hiw.x));
    low.y = pack_bf2(v.z - bf_lo(hiw.y), v.w - bf_hi(hiw.y));
    __nv_bfloat16 *hi, *lo;
    if (which == 0)      { hi = g_ahi; lo = g_alo; }
    else if (which == 1) { hi = g_bhi; lo = g_blo; }
    else if (which == 2) { hi = g_bhi + (size_t)1536 * 512; lo = g_blo + (size_t)1536 * 512; }
    else                 { hi = g_wohi; lo = g_wolo; }
    *(uint2*)(hi + i * 4) = hiw;
    *(uint2*)(lo + i * 4) = low;
}

// ===========================================================================
// Shared bf16x3 HMMA GEMM mainloop: C[128m x 128n] += A[m][k] * B[n][k], K=512.
// 256 threads = 8 warps (4 m-positions x 2 n-positions), warp tile 32m x 64n.
// smem (dynamic 64KB): AH | AL | BH | BL, each 16KB, swizzled 128B rows.
// ===========================================================================
__device__ __forceinline__ void gemm_mainloop_bf16x3(
    const __nv_bfloat16* __restrict__ Ahi, const __nv_bfloat16* __restrict__ Alo,
    const __nv_bfloat16* __restrict__ Bhi, const __nv_bfloat16* __restrict__ Blo,
    int m0, int n0, char* smem, float acc[2][8][4])
{
    char* sAh = smem;
    char* sAl = smem + 16384;
    char* sBh = smem + 32768;
    char* sBl = smem + 49152;
    const uint32_t uAh = smem_u32(sAh), uAl = smem_u32(sAl);
    const uint32_t uBh = smem_u32(sBh), uBl = smem_u32(sBl);

    const int tid = threadIdx.x;
    const int warp = tid >> 5;
    const int lane = tid & 31;
    const int wm0 = (warp & 3) * 32;
    const int wn0 = (warp >> 2) * 64;
    const int lm = lane >> 3;
    const int lr = lane & 7;

    for (int kc = 0; kc < KDIM; kc += 64) {
        __syncthreads();  // prior chunk's ldsm reads done
#pragma unroll
        for (int i = 0; i < 4; ++i) {
            const int a = tid + i * 256;   // granule 0..1023
            const int r = a >> 3;
            const int g = a & 7;
            const uint32_t so = SWZ((uint32_t)(r * 128 + g * 16));
            const size_t asrc = (size_t)(m0 + r) * KDIM + kc + g * 8;
            *(uint4*)(sAh + so) = *(const uint4*)(Ahi + asrc);
            *(uint4*)(sAl + so) = *(const uint4*)(Alo + asrc);
            const size_t bsrc = (size_t)(n0 + r) * KDIM + kc + g * 8;
            *(uint4*)(sBh + so) = *(const uint4*)(Bhi + bsrc);
            *(uint4*)(sBl + so) = *(const uint4*)(Blo + bsrc);
        }
        __syncthreads();

#pragma unroll
        for (int ks = 0; ks < 4; ++ks) {
            uint32_t ah[2][4], al[2][4];
#pragma unroll
            for (int i = 0; i < 2; ++i) {
                const int row = wm0 + 16 * i + ((lm & 1) ? 8 : 0) + lr;
                const int g = 2 * ks + (lm >> 1);
                const uint32_t off = SWZ((uint32_t)(row * 128 + g * 16));
                ldsm4(ah[i], uAh + off);
                ldsm4(al[i], uAl + off);
            }
#pragma unroll
            for (int jp = 0; jp < 4; ++jp) {
                const int nrow = wn0 + 16 * jp + ((lm >= 2) ? 8 : 0) + lr;
                const int g = 2 * ks + (lm & 1);
                const uint32_t off = SWZ((uint32_t)(nrow * 128 + g * 16));
                uint32_t bh[4], bl[4];
                ldsm4(bh, uBh + off);
                ldsm4(bl, uBl + off);
#pragma unroll
                for (int i = 0; i < 2; ++i) {
                    mma16816(acc[i][2 * jp],     ah[i], bh[0], bh[1]);
                    mma16816(acc[i][2 * jp + 1], ah[i], bh[2], bh[3]);
                    mma16816(acc[i][2 * jp],     ah[i], bl[0], bl[1]);
                    mma16816(acc[i][2 * jp + 1], ah[i], bl[2], bl[3]);
                    mma16816(acc[i][2 * jp],     al[i], bh[0], bh[1]);
                    mma16816(acc[i][2 * jp + 1], al[i], bh[2], bh[3]);
                }
            }
        }
    }
}

// ===========================================================================
// Kernel 1: fused QKV + gate projection via HMMA bf16x3.
// Epilogue: q -> scaled split-bf16; k -> split-bf16; v -> fp32; gate -> sigmoid fp32.
// ===========================================================================
__global__ __launch_bounds__(256) void k_gemm1_mma(const float* __restrict__ bg)
{
    extern __shared__ __align__(16) char smem[];
    const int m0 = blockIdx.y * 128;
    const int n0 = blockIdx.x * 128;

    float acc[2][8][4];
#pragma unroll
    for (int i = 0; i < 2; ++i)
#pragma unroll
        for (int j = 0; j < 8; ++j)
#pragma unroll
            for (int c = 0; c < 4; ++c) acc[i][j][c] = 0.f;

    gemm_mainloop_bf16x3(g_ahi, g_alo, g_bhi, g_blo, m0, n0, smem, acc);

    const int warp = threadIdx.x >> 5;
    const int lane = threadIdx.x & 31;
    const int wm0 = (warp & 3) * 32;
    const int wn0 = (warp >> 2) * 64;
    const int qrow = lane >> 2;
    const int nc = 2 * (lane & 3);

    const int region = n0 >> 9;   // 0=q, 1=k, 2=v, 3=gate
    const float qscale = (region == 0) ? 0.125f : 1.0f;

#pragma unroll
    for (int i = 0; i < 2; ++i) {
        const int m = m0 + wm0 + 16 * i + qrow;
#pragma unroll
        for (int j = 0; j < 8; ++j) {
            const int n = n0 + wn0 + 8 * j + nc;
            float v0 = acc[i][j][0] * qscale, v1 = acc[i][j][1] * qscale;
            float v2 = acc[i][j][2] * qscale, v3 = acc[i][j][3] * qscale;
            if (region <= 1) {
                const uint32_t h0 = pack_bf2(v0, v1);
                const uint32_t l0 = pack_bf2(v0 - bf_lo(h0), v1 - bf_hi(h0));
                const uint32_t h1 = pack_bf2(v2, v3);
                const uint32_t l1 = pack_bf2(v2 - bf_lo(h1), v3 - bf_hi(h1));
                const size_t i0 = (size_t)m * 512 + (n - region * 512);
                const size_t i1 = i0 + (size_t)8 * 512;
                if (region == 0) {
                    *(uint32_t*)(&g_qhi[i0]) = h0; *(uint32_t*)(&g_qlo[i0]) = l0;
                    *(uint32_t*)(&g_qhi[i1]) = h1; *(uint32_t*)(&g_qlo[i1]) = l1;
                } else {
                    *(uint32_t*)(&g_khi[i0]) = h0; *(uint32_t*)(&g_klo[i0]) = l0;
                    *(uint32_t*)(&g_khi[i1]) = h1; *(uint32_t*)(&g_klo[i1]) = l1;
                }
            } else {
                if (region == 3) {
                    const float b0v = bg[n - 1536], b1v = bg[n - 1535];
                    v0 = 1.0f / (1.0f + __expf(-(v0 + b0v)));
                    v1 = 1.0f / (1.0f + __expf(-(v1 + b1v)));
                    v2 = 1.0f / (1.0f + __expf(-(v2 + b0v)));
                    v3 = 1.0f / (1.0f + __expf(-(v3 + b1v)));
                }
                *(float2*)(&g_qkvg[(size_t)m * NCOLS + n]) = make_float2(v0, v1);
                *(float2*)(&g_qkvg[(size_t)(m + 8) * NCOLS + n]) = make_float2(v2, v3);
            }
        }
    }
}

// ===========================================================================
// Kernel 1b: V transpose + bf16 hi/lo split.  [token][d] fp32 -> [b,h][d][token]
// ===========================================================================
__global__ __launch_bounds__(256) void k_vsplit()
{
    __shared__ float t[128][65];
    const int tid = threadIdx.x;
    const int tok0 = blockIdx.x * 128;
    const int h = blockIdx.y;
    const int b = blockIdx.z;
    const size_t rbase = (size_t)b * QQ;

#pragma unroll
    for (int i = 0; i < 8; ++i) {
        const int a = tid + i * 256;
        const int r = a >> 4;
        const int c = (a & 15) * 4;
        const float4 v = *(const float4*)(&g_qkvg[(rbase + tok0 + r) * NCOLS + 1024 + h * HD + c]);
        t[r][c + 0] = v.x; t[r][c + 1] = v.y; t[r][c + 2] = v.z; t[r][c + 3] = v.w;
    }
    __syncthreads();

    const int d = tid >> 2;
    const int tq = (tid & 3) * 32;
    uint32_t hiw[16], low[16];
#pragma unroll
    for (int j = 0; j < 16; ++j) {
        const float x0 = t[tq + 2 * j][d];
        const float x1 = t[tq + 2 * j + 1][d];
        const uint32_t ph = pack_bf2(x0, x1);
        hiw[j] = ph;
        low[j] = pack_bf2(x0 - bf_lo(ph), x1 - bf_hi(ph));
    }
    const size_t dst = ((size_t)(b * NH + h) * HD + d) * QQ + tok0 + tq;
#pragma unroll
    for (int j = 0; j < 4; ++j) {
        *(uint4*)(&g_vthi[dst + j * 8]) = make_uint4(hiw[4*j], hiw[4*j+1], hiw[4*j+2], hiw[4*j+3]);
        *(uint4*)(&g_vtlo[dst + j * 8]) = make_uint4(low[4*j], low[4*j+1], low[4*j+2], low[4*j+3]);
    }
}

// ===========================================================================
// Kernel 2: flash attention via mma.sync bf16x3.  128 q-rows, 256 thr, 8 warps.
// Epilogue now emits split-bf16 o (feeds HMMA output projection).
// ===========================================================================
#define FQT 128
#define FKT 64

#define FO_QH 0
#define FO_QL 16384
#define FO_KH 32768
#define FO_KL 40960
#define FO_VH 49152
#define FO_VL 57344
#define FO_TOTAL 65536

__global__ __launch_bounds__(256) void k_flash_mma(const float* __restrict__ bias)
{
    extern __shared__ __align__(16) char smem[];
    char* sQh = smem + FO_QH;
    char* sQl = smem + FO_QL;
    char* sKh = smem + FO_KH;
    char* sKl = smem + FO_KL;
    char* sVh = smem + FO_VH;
    char* sVl = smem + FO_VL;

    const int tid  = threadIdx.x;
    const int warp = tid >> 5;
    const int lane = tid & 31;
    const int q0 = blockIdx.x * FQT;
    const int h  = blockIdx.y;
    const int b  = blockIdx.z;

    const size_t rbase = (size_t)b * QQ;
    const int hq = h * HD;

    const uint32_t uQh = smem_u32(sQh), uQl = smem_u32(sQl);
    const uint32_t uKh = smem_u32(sKh), uKl = smem_u32(sKl);
    const uint32_t uVh = smem_u32(sVh), uVl = smem_u32(sVl);

#pragma unroll
    for (int i = 0; i < 4; ++i) {
        const int a = tid + i * 256;
        const int r = a >> 3;
        const int g = a & 7;
        const size_t src = (rbase + q0 + r) * 512 + hq + g * 8;
        const uint32_t so = SWZ((uint32_t)(r * 128 + g * 16));
        *(uint4*)(sQh + so) = *(const uint4*)(&g_qhi[src]);
        *(uint4*)(sQl + so) = *(const uint4*)(&g_qlo[src]);
    }
    __syncthreads();

    const int lm = lane >> 3;
    const int lr = lane & 7;
    uint32_t qh[4][4], ql[4][4];
#pragma unroll
    for (int ks = 0; ks < 4; ++ks) {
        const int row = warp * 16 + ((lm & 1) ? 8 : 0) + lr;
        const int g = 2 * ks + (lm >> 1);
        const uint32_t off = SWZ((uint32_t)(row * 128 + g * 16));
        ldsm4(qh[ks], uQh + off);
        ldsm4(ql[ks], uQl + off);
    }

    const int qrow = lane >> 2;
    const float* biasb = bias + (size_t)b * QQ * QQ;
    const float* bp0 = biasb + (size_t)(q0 + warp * 16 + qrow) * QQ + 2 * (lane & 3);
    const float* bp1 = bp0 + 8 * QQ;

    const size_t vtb = (size_t)(b * NH + h) * HD;

    float oacc[8][4];
#pragma unroll
    for (int j = 0; j < 8; ++j)
#pragma unroll
        for (int c = 0; c < 4; ++c) oacc[j][c] = 0.f;
    float mrow0 = -3.0e38f, mrow1 = -3.0e38f, lrow0 = 0.f, lrow1 = 0.f;

    for (int kt = 0; kt < QQ / FKT; ++kt) {
        const int k0 = kt * FKT;
        __syncthreads();

#pragma unroll
        for (int i = 0; i < 2; ++i) {
            const int a = tid + i * 256;
            const int r = a >> 3;
            const int g = a & 7;
            const size_t src = (rbase + k0 + r) * 512 + hq + g * 8;
            const uint32_t so = SWZ((uint32_t)(r * 128 + g * 16));
            *(uint4*)(sKh + so) = *(const uint4*)(&g_khi[src]);
            *(uint4*)(sKl + so) = *(const uint4*)(&g_klo[src]);
        }
#pragma unroll
        for (int i = 0; i < 2; ++i) {
            const int a = tid + i * 256;
            const int d = a >> 3;
            const int g = a & 7;
            const size_t src = (vtb + d) * QQ + k0 + g * 8;
            const uint32_t so = SWZ((uint32_t)(d * 128 + g * 16));
            *(uint4*)(sVh + so) = *(const uint4*)(&g_vthi[src]);
            *(uint4*)(sVl + so) = *(const uint4*)(&g_vtlo[src]);
        }
        __syncthreads();

        // ---- S = Q K^T (bf16x3) ----
        float sacc[8][4];
#pragma unroll
        for (int j = 0; j < 8; ++j)
#pragma unroll
            for (int c = 0; c < 4; ++c) sacc[j][c] = 0.f;

#pragma unroll
        for (int ks = 0; ks < 4; ++ks) {
#pragma unroll
            for (int jp = 0; jp < 4; ++jp) {
                const int tok = 16 * jp + ((lm >= 2) ? 8 : 0) + lr;
                const int g = 2 * ks + (lm & 1);
                const uint32_t off = SWZ((uint32_t)(tok * 128 + g * 16));
                uint32_t kh[4], kl[4];
                ldsm4(kh, uKh + off);
                ldsm4(kl, uKl + off);
                mma16816(sacc[2 * jp],     qh[ks], kh[0], kh[1]);
                mma16816(sacc[2 * jp + 1], qh[ks], kh[2], kh[3]);
                mma16816(sacc[2 * jp],     qh[ks], kl[0], kl[1]);
                mma16816(sacc[2 * jp + 1], qh[ks], kl[2], kl[3]);
                mma16816(sacc[2 * jp],     ql[ks], kh[0], kh[1]);
                mma16816(sacc[2 * jp + 1], ql[ks], kh[2], kh[3]);
            }
        }

#pragma unroll
        for (int jt = 0; jt < 8; ++jt) {
            const float2 b0v = *(const float2*)(bp0 + k0 + 8 * jt);
            const float2 b1v = *(const float2*)(bp1 + k0 + 8 * jt);
            sacc[jt][0] += b0v.x; sacc[jt][1] += b0v.y;
            sacc[jt][2] += b1v.x; sacc[jt][3] += b1v.y;
        }

        float mx0 = sacc[0][0], mx1 = sacc[0][2];
#pragma unroll
        for (int jt = 0; jt < 8; ++jt) {
            mx0 = fmaxf(mx0, fmaxf(sacc[jt][0], sacc[jt][1]));
            mx1 = fmaxf(mx1, fmaxf(sacc[jt][2], sacc[jt][3]));
        }
        mx0 = fmaxf(mx0, __shfl_xor_sync(0xffffffffu, mx0, 1));
        mx0 = fmaxf(mx0, __shfl_xor_sync(0xffffffffu, mx0, 2));
        mx1 = fmaxf(mx1, __shfl_xor_sync(0xffffffffu, mx1, 1));
        mx1 = fmaxf(mx1, __shfl_xor_sync(0xffffffffu, mx1, 2));
        const float mn0 = fmaxf(mrow0, mx0);
        const float mn1 = fmaxf(mrow1, mx1);
        const float sc0 = __expf(mrow0 - mn0);
        const float sc1 = __expf(mrow1 - mn1);
        float ls0 = 0.f, ls1 = 0.f;
#pragma unroll
        for (int jt = 0; jt < 8; ++jt) {
            sacc[jt][0] = __expf(sacc[jt][0] - mn0);
            sacc[jt][1] = __expf(sacc[jt][1] - mn0);
            sacc[jt][2] = __expf(sacc[jt][2] - mn1);
            sacc[jt][3] = __expf(sacc[jt][3] - mn1);
            ls0 += sacc[jt][0] + sacc[jt][1];
            ls1 += sacc[jt][2] + sacc[jt][3];
        }
        ls0 += __shfl_xor_sync(0xffffffffu, ls0, 1);
        ls0 += __shfl_xor_sync(0xffffffffu, ls0, 2);
        ls1 += __shfl_xor_sync(0xffffffffu, ls1, 1);
        ls1 += __shfl_xor_sync(0xffffffffu, ls1, 2);
        lrow0 = lrow0 * sc0 + ls0;
        lrow1 = lrow1 * sc1 + ls1;
        mrow0 = mn0;
        mrow1 = mn1;
#pragma unroll
        for (int j = 0; j < 8; ++j) {
            oacc[j][0] *= sc0; oacc[j][1] *= sc0;
            oacc[j][2] *= sc1; oacc[j][3] *= sc1;
        }

        // ---- PV (bf16x3; P register-only) ----
#pragma unroll
        for (int ks = 0; ks < 4; ++ks) {
            uint32_t ph[4], pl[4];
#pragma unroll
            for (int half = 0; half < 2; ++half) {
                const float x0 = sacc[2 * ks + half][0], x1 = sacc[2 * ks + half][1];
                const float y0 = sacc[2 * ks + half][2], y1 = sacc[2 * ks + half][3];
                const uint32_t p0 = pack_bf2(x0, x1);
                const uint32_t p1 = pack_bf2(y0, y1);
                ph[2 * half + 0] = p0;
                ph[2 * half + 1] = p1;
                pl[2 * half + 0] = pack_bf2(x0 - bf_lo(p0), x1 - bf_hi(p0));
                pl[2 * half + 1] = pack_bf2(y0 - bf_lo(p1), y1 - bf_hi(p1));
            }
#pragma unroll
            for (int jdp = 0; jdp < 4; ++jdp) {
                const int d = 16 * jdp + ((lm >= 2) ? 8 : 0) + lr;
                const int g = 2 * ks + (lm & 1);
                const uint32_t off = SWZ((uint32_t)(d * 128 + g * 16));
                uint32_t vh[4], vl[4];
                ldsm4(vh, uVh + off);
                ldsm4(vl, uVl + off);
                mma16816(oacc[2 * jdp],     ph, vh[0], vh[1]);
                mma16816(oacc[2 * jdp + 1], ph, vh[2], vh[3]);
                mma16816(oacc[2 * jdp],     ph, vl[0], vl[1]);
                mma16816(oacc[2 * jdp + 1], ph, vl[2], vl[3]);
                mma16816(oacc[2 * jdp],     pl, vh[0], vh[1]);
                mma16816(oacc[2 * jdp + 1], pl, vh[2], vh[3]);
            }
        }
    }

    // ---- epilogue: normalize + sigmoid gate -> split-bf16 o ----
    {
        const float inv0 = 1.0f / lrow0;
        const float inv1 = 1.0f / lrow1;
        const size_t row0 = rbase + q0 + warp * 16 + qrow;
        const size_t row1 = row0 + 8;
        const int dcol = 2 * (lane & 3);
#pragma unroll
        for (int jd = 0; jd < 8; ++jd) {
            const int d = 8 * jd + dcol;
            const float2 g0 = *(const float2*)(&g_qkvg[row0 * NCOLS + 1536 + hq + d]);
            const float2 g1 = *(const float2*)(&g_qkvg[row1 * NCOLS + 1536 + hq + d]);
            const float o0x = oacc[jd][0] * inv0 * g0.x;
            const float o0y = oacc[jd][1] * inv0 * g0.y;
            const float o1x = oacc[jd][2] * inv1 * g1.x;
            const float o1y = oacc[jd][3] * inv1 * g1.y;
            const uint32_t h0 = pack_bf2(o0x, o0y);
            const uint32_t l0 = pack_bf2(o0x - bf_lo(h0), o0y - bf_hi(h0));
            const uint32_t h1 = pack_bf2(o1x, o1y);
            const uint32_t l1 = pack_bf2(o1x - bf_lo(h1), o1y - bf_hi(h1));
            *(uint32_t*)(&g_ohi[row0 * 512 + hq + d]) = h0;
            *(uint32_t*)(&g_olo[row0 * 512 + hq + d]) = l0;
            *(uint32_t*)(&g_ohi[row1 * 512 + hq + d]) = h1;
            *(uint32_t*)(&g_olo[row1 * 512 + hq + d]) = l1;
        }
    }
}

// ===========================================================================
// Kernel 3: output projection via HMMA bf16x3
// ===========================================================================
__global__ __launch_bounds__(256) void k_gemm2_mma(
    const float* __restrict__ bo, float* __restrict__ out)
{
    extern __shared__ __align__(16) char smem[];
    const int m0 = blockIdx.y * 128;
    const int n0 = blockIdx.x * 128;

    float acc[2][8][4];
#pragma unroll
    for (int i = 0; i < 2; ++i)
#pragma unroll
        for (int j = 0; j < 8; ++j)
#pragma unroll
            for (int c = 0; c < 4; ++c) acc[i][j][c] = 0.f;

    gemm_mainloop_bf16x3(g_ohi, g_olo, g_wohi, g_wolo, m0, n0, smem, acc);

    const int warp = threadIdx.x >> 5;
    const int lane = threadIdx.x & 31;
    const int wm0 = (warp & 3) * 32;
    const int wn0 = (warp >> 2) * 64;
    const int qrow = lane >> 2;
    const int nc = 2 * (lane & 3);

#pragma unroll
    for (int i = 0; i < 2; ++i) {
        const int m = m0 + wm0 + 16 * i + qrow;
#pragma unroll
        for (int j = 0; j < 8; ++j) {
            const int n = n0 + wn0 + 8 * j + nc;
            const float b0v = bo[n], b1v = bo[n + 1];
            *(float2*)(&out[(size_t)m * 512 + n]) =
                make_float2(acc[i][j][0] + b0v, acc[i][j][1] + b1v);
            *(float2*)(&out[(size_t)(m + 8) * 512 + n]) =
                make_float2(acc[i][j][2] + b0v, acc[i][j][3] + b1v);
        }
    }
}

// ---------------------------------------------------------------------------
extern "C" void kernel_launch(void* const* d_in, const int* in_sizes, int n_in,
                              void* d_out, int out_size)
{
    (void)in_sizes; (void)n_in; (void)out_size;
    const float* q_x   = (const float*)d_in[0];
    // d_in[1] = kv_x (unused by the reference)
    const float* bias  = (const float*)d_in[2];
    const float* w_qkv = (const float*)d_in[3];
    const float* w_o   = (const float*)d_in[4];
    const float* b_o   = (const float*)d_in[5];
    const float* w_g   = (const float*)d_in[6];
    const float* b_g   = (const float*)d_in[7];
    float* out = (float*)d_out;

    cudaFuncSetAttribute(k_flash_mma, cudaFuncAttributeMaxDynamicSharedMemorySize,
                         (int)FO_TOTAL);
    cudaFuncSetAttribute(k_gemm1_mma, cudaFuncAttributeMaxDynamicSharedMemorySize, 65536);
    cudaFuncSetAttribute(k_gemm2_mma, cudaFuncAttributeMaxDynamicSharedMemorySize, 65536);

    // input splits: q_x (4096x512), w_qkv (1536x512), w_g (512x512), w_o (512x512)
    k_split<<<MROWS * 512 / 1024, 256>>>(q_x, 0);
    k_split<<<1536 * 512 / 1024, 256>>>(w_qkv, 1);
    k_split<<<512 * 512 / 1024, 256>>>(w_g, 2);
    k_split<<<512 * 512 / 1024, 256>>>(w_o, 3);

    dim3 g1(NCOLS / 128, MROWS / 128);  // (16, 32)
    k_gemm1_mma<<<g1, 256, 65536>>>(b_g);

    dim3 gv(QQ / 128, NH, BB);          // (16, 8, 2)
    k_vsplit<<<gv, 256>>>();

    dim3 g2(QQ / FQT, NH, BB);          // (16, 8, 2)
    k_flash_mma<<<g2, 256, FO_TOTAL>>>(bias);

    dim3 g3(512 / 128, MROWS / 128);    // (4, 32)
    k_gemm2_mma<<<g3, 256, 65536>>>(b_o, out);
}

// round 16
// speedup vs baseline: 2.7679x; 1.2562x over previous
#include <cuda_runtime.h>
#include <cuda_bf16.h>
#include <math.h>
#include <stdint.h>

// Problem dims (fixed)
#define BB 2
#define QQ 2048
#define CQd 512
#define NH 8
#define HD 64
#define MROWS (BB * QQ)   // 4096
#define NCOLS 2048        // layout inside g_qkvg: [q|k|v|gate] (q/k slots unused)
#define KDIM 512

// Scratch (no allocations allowed -> device globals)
__device__ float g_qkvg[(size_t)MROWS * NCOLS];          // v (fp32) | gate (fp32)
__device__ __nv_bfloat16 g_ahi[(size_t)MROWS * 512];     // q_x split
__device__ __nv_bfloat16 g_alo[(size_t)MROWS * 512];
__device__ __nv_bfloat16 g_bhi[(size_t)2048 * 512];      // [w_qkv; w_g] split
__device__ __nv_bfloat16 g_blo[(size_t)2048 * 512];
__device__ __nv_bfloat16 g_wohi[(size_t)512 * 512];      // w_o split
__device__ __nv_bfloat16 g_wolo[(size_t)512 * 512];
__device__ __nv_bfloat16 g_qhi[(size_t)MROWS * 512];     // Q split (scaled by 1/8)
__device__ __nv_bfloat16 g_qlo[(size_t)MROWS * 512];
__device__ __nv_bfloat16 g_khi[(size_t)MROWS * 512];     // K split
__device__ __nv_bfloat16 g_klo[(size_t)MROWS * 512];
__device__ __nv_bfloat16 g_vthi[(size_t)BB * NH * HD * QQ]; // V^T split: [b][h][d][token]
__device__ __nv_bfloat16 g_vtlo[(size_t)BB * NH * HD * QQ];
__device__ __nv_bfloat16 g_ohi[(size_t)MROWS * 512];     // gated attention out, split
__device__ __nv_bfloat16 g_olo[(size_t)MROWS * 512];

// ===========================================================================
// Baseline-PTX helpers (sm_80-era: valid on compute_103 base target)
// ===========================================================================
__device__ __forceinline__ uint32_t smem_u32(const void* p) {
    uint32_t a;
    asm("{ .reg .u64 t; cvta.to.shared.u64 t, %1; cvt.u32.u64 %0, t; }"
        : "=r"(a) : "l"(p));
    return a;
}

__device__ __forceinline__ void ldsm4(uint32_t* r, uint32_t addr) {
    asm volatile("ldmatrix.sync.aligned.m8n8.x4.shared.b16 {%0,%1,%2,%3}, [%4];"
                 : "=r"(r[0]), "=r"(r[1]), "=r"(r[2]), "=r"(r[3]) : "r"(addr));
}

__device__ __forceinline__ void mma16816(float* c, const uint32_t* a,
                                         uint32_t b0, uint32_t b1) {
    asm volatile(
        "mma.sync.aligned.m16n8k16.row.col.f32.bf16.bf16.f32 "
        "{%0,%1,%2,%3}, {%4,%5,%6,%7}, {%8,%9}, {%0,%1,%2,%3};"
        : "+f"(c[0]), "+f"(c[1]), "+f"(c[2]), "+f"(c[3])
        : "r"(a[0]), "r"(a[1]), "r"(a[2]), "r"(a[3]), "r"(b0), "r"(b1));
}

__device__ __forceinline__ uint32_t pack_bf2(float x_even, float x_odd) {
    uint32_t r;
    asm("cvt.rn.bf16x2.f32 %0, %1, %2;" : "=r"(r) : "f"(x_odd), "f"(x_even));
    return r;
}
__device__ __forceinline__ float bf_lo(uint32_t p) { return __uint_as_float(p << 16); }
__device__ __forceinline__ float bf_hi(uint32_t p) { return __uint_as_float(p & 0xffff0000u); }

#define SWZ(byte_off) ((byte_off) ^ (((byte_off) >> 3) & 0x70))

// cp.async 16B (cg = bypass L1)
__device__ __forceinline__ void cpa16(uint32_t saddr, const void* gptr) {
    asm volatile("cp.async.cg.shared.global [%0], [%1], 16;"
                 :: "r"(saddr), "l"(__cvta_generic_to_global(gptr)) : "memory");
}
#define CP_COMMIT() asm volatile("cp.async.commit_group;" ::: "memory")
#define CP_WAIT1()  asm volatile("cp.async.wait_group 1;" ::: "memory")

// ===========================================================================
// Merged split kernel: fp32 -> bf16 hi/lo for q_x, w_qkv, w_g, w_o.
// Grid 3328: [0,2048) q_x, [2048,2816) w_qkv, [2816,3072) w_g, [3072,3328) w_o
// ===========================================================================
__global__ __launch_bounds__(256) void k_split_all(
    const float* __restrict__ qx, const float* __restrict__ wqkv,
    const float* __restrict__ wg, const float* __restrict__ wo)
{
    const int bid = blockIdx.x;
    const float* src;
    __nv_bfloat16 *hi, *lo;
    size_t base;
    if (bid < 2048)      { src = qx;   hi = g_ahi;  lo = g_alo;  base = (size_t)bid; }
    else if (bid < 2816) { src = wqkv; hi = g_bhi;  lo = g_blo;  base = (size_t)(bid - 2048); }
    else if (bid < 3072) { src = wg;   hi = g_bhi + (size_t)1536 * 512;
                           lo = g_blo + (size_t)1536 * 512;      base = (size_t)(bid - 2816); }
    else                 { src = wo;   hi = g_wohi; lo = g_wolo; base = (size_t)(bid - 3072); }
    const size_t i = base * 256 + threadIdx.x;   // float4 index
    const float4 v = *(const float4*)(src + i * 4);
    uint2 hiw, low;
    hiw.x = pack_bf2(v.x, v.y);
    hiw.y = pack_bf2(v.z, v.w);
    low.x = pack_bf2(v.x - bf_lo(hiw.x), v.y - bf_hi(hiw.x));
    low.y = pack_bf2(v.z - bf_lo(hiw.y), v.w - bf_hi(hiw.y));
    *(uint2*)(hi + i * 4) = hiw;
    *(uint2*)(lo + i * 4) = low;
}

// ===========================================================================
// Shared bf16x3 HMMA GEMM mainloop, cp.async double-buffered.
// C[128m x 128n] += A[m][k]*B[n][k], K=512, chunks of 64.
// 256 thr = 8 warps (4m x 2n), warp tile 32m x 64n.
// smem: 2 stages x 64KB; stage: AH|AL|BH|BL (16KB each), swizzled 128B rows.
// ===========================================================================
#define G_STAGE 65536
#define G_SMEM  (2 * G_STAGE)

__device__ __forceinline__ void gemm_mainloop_db(
    const __nv_bfloat16* __restrict__ Ahi, const __nv_bfloat16* __restrict__ Alo,
    const __nv_bfloat16* __restrict__ Bhi, const __nv_bfloat16* __restrict__ Blo,
    int m0, int n0, char* smem, float acc[2][8][4])
{
    const uint32_t uS = smem_u32(smem);
    const int tid = threadIdx.x;
    const int warp = tid >> 5;
    const int lane = tid & 31;
    const int wm0 = (warp & 3) * 32;
    const int wn0 = (warp >> 2) * 64;
    const int lm = lane >> 3;
    const int lr = lane & 7;

#define G_ISSUE(s, kc) do { \
    const uint32_t _b = uS + (s) * G_STAGE; \
    _Pragma("unroll") \
    for (int _i = 0; _i < 4; ++_i) { \
        const int _a = tid + _i * 256; \
        const int _r = _a >> 3; \
        const int _g = _a & 7; \
        const uint32_t _so = SWZ((uint32_t)(_r * 128 + _g * 16)); \
        const size_t _ao = (size_t)(m0 + _r) * KDIM + (kc) + _g * 8; \
        const size_t _bo = (size_t)(n0 + _r) * KDIM + (kc) + _g * 8; \
        cpa16(_b + _so,         Ahi + _ao); \
        cpa16(_b + 16384 + _so, Alo + _ao); \
        cpa16(_b + 32768 + _so, Bhi + _bo); \
        cpa16(_b + 49152 + _so, Blo + _bo); \
    } } while (0)

    G_ISSUE(0, 0);  CP_COMMIT();
    G_ISSUE(1, 64); CP_COMMIT();

    for (int c = 0; c < 8; ++c) {
        CP_WAIT1();
        __syncthreads();
        const uint32_t uAh = uS + (c & 1) * G_STAGE;
        const uint32_t uAl = uAh + 16384;
        const uint32_t uBh = uAh + 32768;
        const uint32_t uBl = uAh + 49152;

#pragma unroll
        for (int ks = 0; ks < 4; ++ks) {
            uint32_t ah[2][4], al[2][4];
#pragma unroll
            for (int i = 0; i < 2; ++i) {
                const int row = wm0 + 16 * i + ((lm & 1) ? 8 : 0) + lr;
                const int g = 2 * ks + (lm >> 1);
                const uint32_t off = SWZ((uint32_t)(row * 128 + g * 16));
                ldsm4(ah[i], uAh + off);
                ldsm4(al[i], uAl + off);
            }
#pragma unroll
            for (int jp = 0; jp < 4; ++jp) {
                const int nrow = wn0 + 16 * jp + ((lm >= 2) ? 8 : 0) + lr;
                const int g = 2 * ks + (lm & 1);
                const uint32_t off = SWZ((uint32_t)(nrow * 128 + g * 16));
                uint32_t bh[4], bl[4];
                ldsm4(bh, uBh + off);
                ldsm4(bl, uBl + off);
#pragma unroll
                for (int i = 0; i < 2; ++i) {
                    mma16816(acc[i][2 * jp],     ah[i], bh[0], bh[1]);
                    mma16816(acc[i][2 * jp + 1], ah[i], bh[2], bh[3]);
                    mma16816(acc[i][2 * jp],     ah[i], bl[0], bl[1]);
                    mma16816(acc[i][2 * jp + 1], ah[i], bl[2], bl[3]);
                    mma16816(acc[i][2 * jp],     al[i], bh[0], bh[1]);
                    mma16816(acc[i][2 * jp + 1], al[i], bh[2], bh[3]);
                }
            }
        }
        __syncthreads();
        if (c + 2 < 8) G_ISSUE(c & 1, (c + 2) * 64);
        CP_COMMIT();   // possibly empty: keeps wait_group invariant
    }
#undef G_ISSUE
}

// ===========================================================================
// Kernel 1: fused QKV + gate projection via HMMA bf16x3.
// ===========================================================================
__global__ __launch_bounds__(256) void k_gemm1_mma(const float* __restrict__ bg)
{
    extern __shared__ __align__(16) char smem[];
    const int m0 = blockIdx.y * 128;
    const int n0 = blockIdx.x * 128;

    float acc[2][8][4];
#pragma unroll
    for (int i = 0; i < 2; ++i)
#pragma unroll
        for (int j = 0; j < 8; ++j)
#pragma unroll
            for (int c = 0; c < 4; ++c) acc[i][j][c] = 0.f;

    gemm_mainloop_db(g_ahi, g_alo, g_bhi, g_blo, m0, n0, smem, acc);

    const int warp = threadIdx.x >> 5;
    const int lane = threadIdx.x & 31;
    const int wm0 = (warp & 3) * 32;
    const int wn0 = (warp >> 2) * 64;
    const int qrow = lane >> 2;
    const int nc = 2 * (lane & 3);

    const int region = n0 >> 9;   // 0=q, 1=k, 2=v, 3=gate
    const float qscale = (region == 0) ? 0.125f : 1.0f;

#pragma unroll
    for (int i = 0; i < 2; ++i) {
        const int m = m0 + wm0 + 16 * i + qrow;
#pragma unroll
        for (int j = 0; j < 8; ++j) {
            const int n = n0 + wn0 + 8 * j + nc;
            float v0 = acc[i][j][0] * qscale, v1 = acc[i][j][1] * qscale;
            float v2 = acc[i][j][2] * qscale, v3 = acc[i][j][3] * qscale;
            if (region <= 1) {
                const uint32_t h0 = pack_bf2(v0, v1);
                const uint32_t l0 = pack_bf2(v0 - bf_lo(h0), v1 - bf_hi(h0));
                const uint32_t h1 = pack_bf2(v2, v3);
                const uint32_t l1 = pack_bf2(v2 - bf_lo(h1), v3 - bf_hi(h1));
                const size_t i0 = (size_t)m * 512 + (n - region * 512);
                const size_t i1 = i0 + (size_t)8 * 512;
                if (region == 0) {
                    *(uint32_t*)(&g_qhi[i0]) = h0; *(uint32_t*)(&g_qlo[i0]) = l0;
                    *(uint32_t*)(&g_qhi[i1]) = h1; *(uint32_t*)(&g_qlo[i1]) = l1;
                } else {
                    *(uint32_t*)(&g_khi[i0]) = h0; *(uint32_t*)(&g_klo[i0]) = l0;
                    *(uint32_t*)(&g_khi[i1]) = h1; *(uint32_t*)(&g_klo[i1]) = l1;
                }
            } else {
                if (region == 3) {
                    const float b0v = bg[n - 1536], b1v = bg[n - 1535];
                    v0 = 1.0f / (1.0f + __expf(-(v0 + b0v)));
                    v1 = 1.0f / (1.0f + __expf(-(v1 + b1v)));
                    v2 = 1.0f / (1.0f + __expf(-(v2 + b0v)));
                    v3 = 1.0f / (1.0f + __expf(-(v3 + b1v)));
                }
                *(float2*)(&g_qkvg[(size_t)m * NCOLS + n]) = make_float2(v0, v1);
                *(float2*)(&g_qkvg[(size_t)(m + 8) * NCOLS + n]) = make_float2(v2, v3);
            }
        }
    }
}

// ===========================================================================
// Kernel 1b: V transpose + bf16 hi/lo split.  [token][d] fp32 -> [b,h][d][token]
// ===========================================================================
__global__ __launch_bounds__(256) void k_vsplit()
{
    __shared__ float t[128][65];
    const int tid = threadIdx.x;
    const int tok0 = blockIdx.x * 128;
    const int h = blockIdx.y;
    const int b = blockIdx.z;
    const size_t rbase = (size_t)b * QQ;

#pragma unroll
    for (int i = 0; i < 8; ++i) {
        const int a = tid + i * 256;
        const int r = a >> 4;
        const int c = (a & 15) * 4;
        const float4 v = *(const float4*)(&g_qkvg[(rbase + tok0 + r) * NCOLS + 1024 + h * HD + c]);
        t[r][c + 0] = v.x; t[r][c + 1] = v.y; t[r][c + 2] = v.z; t[r][c + 3] = v.w;
    }
    __syncthreads();

    const int d = tid >> 2;
    const int tq = (tid & 3) * 32;
    uint32_t hiw[16], low[16];
#pragma unroll
    for (int j = 0; j < 16; ++j) {
        const float x0 = t[tq + 2 * j][d];
        const float x1 = t[tq + 2 * j + 1][d];
        const uint32_t ph = pack_bf2(x0, x1);
        hiw[j] = ph;
        low[j] = pack_bf2(x0 - bf_lo(ph), x1 - bf_hi(ph));
    }
    const size_t dst = ((size_t)(b * NH + h) * HD + d) * QQ + tok0 + tq;
#pragma unroll
    for (int j = 0; j < 4; ++j) {
        *(uint4*)(&g_vthi[dst + j * 8]) = make_uint4(hiw[4*j], hiw[4*j+1], hiw[4*j+2], hiw[4*j+3]);
        *(uint4*)(&g_vtlo[dst + j * 8]) = make_uint4(low[4*j], low[4*j+1], low[4*j+2], low[4*j+3]);
    }
}

// ===========================================================================
// Kernel 2: flash attention, bf16x3 HMMA, cp.async double-buffered K/V.
// 128 q-rows x (head, batch); 256 thr = 8 warps x 16 rows.
// smem 96KB: Q (QH|QL, 32KB) + 2 stages x 32KB (KH|KL|VH|VL).
// ===========================================================================
#define FQT 128
#define FKT 64
#define F_QBASE 0
#define F_STAGE0 32768
#define F_STAGE 32768
#define F_TOTAL 98304

__global__ __launch_bounds__(256) void k_flash_mma(const float* __restrict__ bias)
{
    extern __shared__ __align__(16) char smem[];
    const uint32_t uS = smem_u32(smem);

    const int tid  = threadIdx.x;
    const int warp = tid >> 5;
    const int lane = tid & 31;
    const int q0 = blockIdx.x * FQT;
    const int h  = blockIdx.y;
    const int b  = blockIdx.z;

    const size_t rbase = (size_t)b * QQ;
    const int hq = h * HD;
    const size_t vtb = (size_t)(b * NH + h) * HD;

#define F_ISSUE(s, k0) do { \
    const uint32_t _b = uS + F_STAGE0 + (s) * F_STAGE; \
    _Pragma("unroll") \
    for (int _i = 0; _i < 2; ++_i) { \
        const int _a = tid + _i * 256; \
        const int _r = _a >> 3; \
        const int _g = _a & 7; \
        const uint32_t _so = SWZ((uint32_t)(_r * 128 + _g * 16)); \
        const size_t _ko = (rbase + (k0) + _r) * 512 + hq + _g * 8; \
        const size_t _vo = (vtb + _r) * QQ + (k0) + _g * 8; \
        cpa16(_b + _so,         g_khi + _ko); \
        cpa16(_b + 8192 + _so,  g_klo + _ko); \
        cpa16(_b + 16384 + _so, g_vthi + _vo); \
        cpa16(_b + 24576 + _so, g_vtlo + _vo); \
    } } while (0)

    // prologue: start K/V tiles 0,1 streaming, then stage Q
    F_ISSUE(0, 0);   CP_COMMIT();
    F_ISSUE(1, FKT); CP_COMMIT();

    char* sQh = smem + F_QBASE;
    char* sQl = smem + F_QBASE + 16384;
#pragma unroll
    for (int i = 0; i < 4; ++i) {
        const int a = tid + i * 256;
        const int r = a >> 3;
        const int g = a & 7;
        const size_t src = (rbase + q0 + r) * 512 + hq + g * 8;
        const uint32_t so = SWZ((uint32_t)(r * 128 + g * 16));
        *(uint4*)(sQh + so) = *(const uint4*)(&g_qhi[src]);
        *(uint4*)(sQl + so) = *(const uint4*)(&g_qlo[src]);
    }
    __syncthreads();

    const int lm = lane >> 3;
    const int lr = lane & 7;
    const uint32_t uQh = uS + F_QBASE, uQl = uS + F_QBASE + 16384;
    uint32_t qh[4][4], ql[4][4];
#pragma unroll
    for (int ks = 0; ks < 4; ++ks) {
        const int row = warp * 16 + ((lm & 1) ? 8 : 0) + lr;
        const int g = 2 * ks + (lm >> 1);
        const uint32_t off = SWZ((uint32_t)(row * 128 + g * 16));
        ldsm4(qh[ks], uQh + off);
        ldsm4(ql[ks], uQl + off);
    }

    const int qrow = lane >> 2;
    const float* biasb = bias + (size_t)b * QQ * QQ;
    const float* bp0 = biasb + (size_t)(q0 + warp * 16 + qrow) * QQ + 2 * (lane & 3);
    const float* bp1 = bp0 + 8 * QQ;

    float oacc[8][4];
#pragma unroll
    for (int j = 0; j < 8; ++j)
#pragma unroll
        for (int c = 0; c < 4; ++c) oacc[j][c] = 0.f;
    float mrow0 = -3.0e38f, mrow1 = -3.0e38f, lrow0 = 0.f, lrow1 = 0.f;

    for (int kt = 0; kt < QQ / FKT; ++kt) {
        const int k0 = kt * FKT;
        CP_WAIT1();
        __syncthreads();
        const uint32_t uKh = uS + F_STAGE0 + (kt & 1) * F_STAGE;
        const uint32_t uKl = uKh + 8192;
        const uint32_t uVh = uKh + 16384;
        const uint32_t uVl = uKh + 24576;

        // ---- S = Q K^T (bf16x3) ----
        float sacc[8][4];
#pragma unroll
        for (int j = 0; j < 8; ++j)
#pragma unroll
            for (int c = 0; c < 4; ++c) sacc[j][c] = 0.f;

#pragma unroll
        for (int ks = 0; ks < 4; ++ks) {
#pragma unroll
            for (int jp = 0; jp < 4; ++jp) {
                const int tok = 16 * jp + ((lm >= 2) ? 8 : 0) + lr;
                const int g = 2 * ks + (lm & 1);
                const uint32_t off = SWZ((uint32_t)(tok * 128 + g * 16));
                uint32_t kh[4], kl[4];
                ldsm4(kh, uKh + off);
                ldsm4(kl, uKl + off);
                mma16816(sacc[2 * jp],     qh[ks], kh[0], kh[1]);
                mma16816(sacc[2 * jp + 1], qh[ks], kh[2], kh[3]);
                mma16816(sacc[2 * jp],     qh[ks], kl[0], kl[1]);
                mma16816(sacc[2 * jp + 1], qh[ks], kl[2], kl[3]);
                mma16816(sacc[2 * jp],     ql[ks], kh[0], kh[1]);
                mma16816(sacc[2 * jp + 1], ql[ks], kh[2], kh[3]);
            }
        }

#pragma unroll
        for (int jt = 0; jt < 8; ++jt) {
            const float2 b0v = *(const float2*)(bp0 + k0 + 8 * jt);
            const float2 b1v = *(const float2*)(bp1 + k0 + 8 * jt);
            sacc[jt][0] += b0v.x; sacc[jt][1] += b0v.y;
            sacc[jt][2] += b1v.x; sacc[jt][3] += b1v.y;
        }

        float mx0 = sacc[0][0], mx1 = sacc[0][2];
#pragma unroll
        for (int jt = 0; jt < 8; ++jt) {
            mx0 = fmaxf(mx0, fmaxf(sacc[jt][0], sacc[jt][1]));
            mx1 = fmaxf(mx1, fmaxf(sacc[jt][2], sacc[jt][3]));
        }
        mx0 = fmaxf(mx0, __shfl_xor_sync(0xffffffffu, mx0, 1));
        mx0 = fmaxf(mx0, __shfl_xor_sync(0xffffffffu, mx0, 2));
        mx1 = fmaxf(mx1, __shfl_xor_sync(0xffffffffu, mx1, 1));
        mx1 = fmaxf(mx1, __shfl_xor_sync(0xffffffffu, mx1, 2));
        const float mn0 = fmaxf(mrow0, mx0);
        const float mn1 = fmaxf(mrow1, mx1);
        const float sc0 = __expf(mrow0 - mn0);
        const float sc1 = __expf(mrow1 - mn1);
        float ls0 = 0.f, ls1 = 0.f;
#pragma unroll
        for (int jt = 0; jt < 8; ++jt) {
            sacc[jt][0] = __expf(sacc[jt][0] - mn0);
            sacc[jt][1] = __expf(sacc[jt][1] - mn0);
            sacc[jt][2] = __expf(sacc[jt][2] - mn1);
            sacc[jt][3] = __expf(sacc[jt][3] - mn1);
            ls0 += sacc[jt][0] + sacc[jt][1];
            ls1 += sacc[jt][2] + sacc[jt][3];
        }
        ls0 += __shfl_xor_sync(0xffffffffu, ls0, 1);
        ls0 += __shfl_xor_sync(0xffffffffu, ls0, 2);
        ls1 += __shfl_xor_sync(0xffffffffu, ls1, 1);
        ls1 += __shfl_xor_sync(0xffffffffu, ls1, 2);
        lrow0 = lrow0 * sc0 + ls0;
        lrow1 = lrow1 * sc1 + ls1;
        mrow0 = mn0;
        mrow1 = mn1;
#pragma unroll
        for (int j = 0; j < 8; ++j) {
            oacc[j][0] *= sc0; oacc[j][1] *= sc0;
            oacc[j][2] *= sc1; oacc[j][3] *= sc1;
        }

        // ---- PV (bf16x3; P register-only via C->A frag identity) ----
#pragma unroll
        for (int ks = 0; ks < 4; ++ks) {
            uint32_t ph[4], pl[4];
#pragma unroll
            for (int half = 0; half < 2; ++half) {
                const float x0 = sacc[2 * ks + half][0], x1 = sacc[2 * ks + half][1];
                const float y0 = sacc[2 * ks + half][2], y1 = sacc[2 * ks + half][3];
                const uint32_t p0 = pack_bf2(x0, x1);
                const uint32_t p1 = pack_bf2(y0, y1);
                ph[2 * half + 0] = p0;
                ph[2 * half + 1] = p1;
                pl[2 * half + 0] = pack_bf2(x0 - bf_lo(p0), x1 - bf_hi(p0));
                pl[2 * half + 1] = pack_bf2(y0 - bf_lo(p1), y1 - bf_hi(p1));
            }
#pragma unroll
            for (int jdp = 0; jdp < 4; ++jdp) {
                const int d = 16 * jdp + ((lm >= 2) ? 8 : 0) + lr;
                const int g = 2 * ks + (lm & 1);
                const uint32_t off = SWZ((uint32_t)(d * 128 + g * 16));
                uint32_t vh[4], vl[4];
                ldsm4(vh, uVh + off);
                ldsm4(vl, uVl + off);
                mma16816(oacc[2 * jdp],     ph, vh[0], vh[1]);
                mma16816(oacc[2 * jdp + 1], ph, vh[2], vh[3]);
                mma16816(oacc[2 * jdp],     ph, vl[0], vl[1]);
                mma16816(oacc[2 * jdp + 1], ph, vl[2], vl[3]);
                mma16816(oacc[2 * jdp],     pl, vh[0], vh[1]);
                mma16816(oacc[2 * jdp + 1], pl, vh[2], vh[3]);
            }
        }

        __syncthreads();   // all warps done reading stage kt&1
        if (kt + 2 < QQ / FKT) F_ISSUE(kt & 1, (kt + 2) * FKT);
        CP_COMMIT();       // possibly empty
    }
#undef F_ISSUE

    // ---- epilogue: normalize + sigmoid gate -> split-bf16 o ----
    {
        const float inv0 = 1.0f / lrow0;
        const float inv1 = 1.0f / lrow1;
        const size_t row0 = rbase + q0 + warp * 16 + qrow;
        const size_t row1 = row0 + 8;
        const int dcol = 2 * (lane & 3);
#pragma unroll
        for (int jd = 0; jd < 8; ++jd) {
            const int d = 8 * jd + dcol;
            const float2 g0 = *(const float2*)(&g_qkvg[row0 * NCOLS + 1536 + hq + d]);
            const float2 g1 = *(const float2*)(&g_qkvg[row1 * NCOLS + 1536 + hq + d]);
            const float o0x = oacc[jd][0] * inv0 * g0.x;
            const float o0y = oacc[jd][1] * inv0 * g0.y;
            const float o1x = oacc[jd][2] * inv1 * g1.x;
            const float o1y = oacc[jd][3] * inv1 * g1.y;
            const uint32_t h0 = pack_bf2(o0x, o0y);
            const uint32_t l0 = pack_bf2(o0x - bf_lo(h0), o0y - bf_hi(h0));
            const uint32_t h1 = pack_bf2(o1x, o1y);
            const uint32_t l1 = pack_bf2(o1x - bf_lo(h1), o1y - bf_hi(h1));
            *(uint32_t*)(&g_ohi[row0 * 512 + hq + d]) = h0;
            *(uint32_t*)(&g_olo[row0 * 512 + hq + d]) = l0;
            *(uint32_t*)(&g_ohi[row1 * 512 + hq + d]) = h1;
            *(uint32_t*)(&g_olo[row1 * 512 + hq + d]) = l1;
        }
    }
}

// ===========================================================================
// Kernel 3: output projection via HMMA bf16x3
// ===========================================================================
__global__ __launch_bounds__(256) void k_gemm2_mma(
    const float* __restrict__ bo, float* __restrict__ out)
{
    extern __shared__ __align__(16) char smem[];
    const int m0 = blockIdx.y * 128;
    const int n0 = blockIdx.x * 128;

    float acc[2][8][4];
#pragma unroll
    for (int i = 0; i < 2; ++i)
#pragma unroll
        for (int j = 0; j < 8; ++j)
#pragma unroll
            for (int c = 0; c < 4; ++c) acc[i][j][c] = 0.f;

    gemm_mainloop_db(g_ohi, g_olo, g_wohi, g_wolo, m0, n0, smem, acc);

    const int warp = threadIdx.x >> 5;
    const int lane = threadIdx.x & 31;
    const int wm0 = (warp & 3) * 32;
    const int wn0 = (warp >> 2) * 64;
    const int qrow = lane >> 2;
    const int nc = 2 * (lane & 3);

#pragma unroll
    for (int i = 0; i < 2; ++i) {
        const int m = m0 + wm0 + 16 * i + qrow;
#pragma unroll
        for (int j = 0; j < 8; ++j) {
            const int n = n0 + wn0 + 8 * j + nc;
            const float b0v = bo[n], b1v = bo[n + 1];
            *(float2*)(&out[(size_t)m * 512 + n]) =
                make_float2(acc[i][j][0] + b0v, acc[i][j][1] + b1v);
            *(float2*)(&out[(size_t)(m + 8) * 512 + n]) =
                make_float2(acc[i][j][2] + b0v, acc[i][j][3] + b1v);
        }
    }
}

// ---------------------------------------------------------------------------
extern "C" void kernel_launch(void* const* d_in, const int* in_sizes, int n_in,
                              void* d_out, int out_size)
{
    (void)in_sizes; (void)n_in; (void)out_size;
    const float* q_x   = (const float*)d_in[0];
    // d_in[1] = kv_x (unused by the reference)
    const float* bias  = (const float*)d_in[2];
    const float* w_qkv = (const float*)d_in[3];
    const float* w_o   = (const float*)d_in[4];
    const float* b_o   = (const float*)d_in[5];
    const float* w_g   = (const float*)d_in[6];
    const float* b_g   = (const float*)d_in[7];
    float* out = (float*)d_out;

    cudaFuncSetAttribute(k_flash_mma, cudaFuncAttributeMaxDynamicSharedMemorySize,
                         (int)F_TOTAL);
    cudaFuncSetAttribute(k_gemm1_mma, cudaFuncAttributeMaxDynamicSharedMemorySize,
                         (int)G_SMEM);
    cudaFuncSetAttribute(k_gemm2_mma, cudaFuncAttributeMaxDynamicSharedMemorySize,
                         (int)G_SMEM);

    k_split_all<<<3328, 256>>>(q_x, w_qkv, w_g, w_o);

    dim3 g1(NCOLS / 128, MROWS / 128);  // (16, 32)
    k_gemm1_mma<<<g1, 256, G_SMEM>>>(b_g);

    dim3 gv(QQ / 128, NH, BB);          // (16, 8, 2)
    k_vsplit<<<gv, 256>>>();

    dim3 g2(QQ / FQT, NH, BB);          // (16, 8, 2)
    k_flash_mma<<<g2, 256, F_TOTAL>>>(bias);

    dim3 g3(512 / 128, MROWS / 128);    // (4, 32)
    k_gemm2_mma<<<g3, 256, G_SMEM>>>(b_o, out);
}

// round 17
// speedup vs baseline: 2.9837x; 1.0780x over previous
#include <cuda_runtime.h>
#include <cuda_bf16.h>
#include <math.h>
#include <stdint.h>

// Problem dims (fixed)
#define BB 2
#define QQ 2048
#define CQd 512
#define NH 8
#define HD 64
#define MROWS (BB * QQ)   // 4096
#define NCOLS 2048        // layout inside g_qkvg: [q|k|v|gate] (q/k slots unused)
#define KDIM 512
#define LOG2E 1.4426950408889634f

// Scratch (no allocations allowed -> device globals)
__device__ float g_qkvg[(size_t)MROWS * NCOLS];          // v (fp32) | gate (fp32)
__device__ __nv_bfloat16 g_ahi[(size_t)MROWS * 512];     // q_x split
__device__ __nv_bfloat16 g_alo[(size_t)MROWS * 512];
__device__ __nv_bfloat16 g_bhi[(size_t)2048 * 512];      // [w_qkv; w_g] split
__device__ __nv_bfloat16 g_blo[(size_t)2048 * 512];
__device__ __nv_bfloat16 g_wohi[(size_t)512 * 512];      // w_o split
__device__ __nv_bfloat16 g_wolo[(size_t)512 * 512];
__device__ __nv_bfloat16 g_qhi[(size_t)MROWS * 512];     // Q split (scaled by log2e/8)
__device__ __nv_bfloat16 g_qlo[(size_t)MROWS * 512];
__device__ __nv_bfloat16 g_khi[(size_t)MROWS * 512];     // K split
__device__ __nv_bfloat16 g_klo[(size_t)MROWS * 512];
__device__ __nv_bfloat16 g_vthi[(size_t)BB * NH * HD * QQ]; // V^T split: [b][h][d][token]
__device__ __nv_bfloat16 g_vtlo[(size_t)BB * NH * HD * QQ];
__device__ __nv_bfloat16 g_ohi[(size_t)MROWS * 512];     // gated attention out, split
__device__ __nv_bfloat16 g_olo[(size_t)MROWS * 512];

// ===========================================================================
// Baseline-PTX helpers (sm_80-era: valid on compute_103 base target)
// ===========================================================================
__device__ __forceinline__ uint32_t smem_u32(const void* p) {
    uint32_t a;
    asm("{ .reg .u64 t; cvta.to.shared.u64 t, %1; cvt.u32.u64 %0, t; }"
        : "=r"(a) : "l"(p));
    return a;
}

__device__ __forceinline__ void ldsm4(uint32_t* r, uint32_t addr) {
    asm volatile("ldmatrix.sync.aligned.m8n8.x4.shared.b16 {%0,%1,%2,%3}, [%4];"
                 : "=r"(r[0]), "=r"(r[1]), "=r"(r[2]), "=r"(r[3]) : "r"(addr));
}

__device__ __forceinline__ void mma16816(float* c, const uint32_t* a,
                                         uint32_t b0, uint32_t b1) {
    asm volatile(
        "mma.sync.aligned.m16n8k16.row.col.f32.bf16.bf16.f32 "
        "{%0,%1,%2,%3}, {%4,%5,%6,%7}, {%8,%9}, {%0,%1,%2,%3};"
        : "+f"(c[0]), "+f"(c[1]), "+f"(c[2]), "+f"(c[3])
        : "r"(a[0]), "r"(a[1]), "r"(a[2]), "r"(a[3]), "r"(b0), "r"(b1));
}

__device__ __forceinline__ uint32_t pack_bf2(float x_even, float x_odd) {
    uint32_t r;
    asm("cvt.rn.bf16x2.f32 %0, %1, %2;" : "=r"(r) : "f"(x_odd), "f"(x_even));
    return r;
}
__device__ __forceinline__ float bf_lo(uint32_t p) { return __uint_as_float(p << 16); }
__device__ __forceinline__ float bf_hi(uint32_t p) { return __uint_as_float(p & 0xffff0000u); }

// fast exp2 via MUFU (flag-independent)
__device__ __forceinline__ float ex2(float x) {
    float y; asm("ex2.approx.ftz.f32 %0, %1;" : "=f"(y) : "f"(x)); return y;
}

#define SWZ(byte_off) ((byte_off) ^ (((byte_off) >> 3) & 0x70))

// cp.async 16B (cg = bypass L1)
__device__ __forceinline__ void cpa16(uint32_t saddr, const void* gptr) {
    asm volatile("cp.async.cg.shared.global [%0], [%1], 16;"
                 :: "r"(saddr), "l"(__cvta_generic_to_global(gptr)) : "memory");
}
#define CP_COMMIT() asm volatile("cp.async.commit_group;" ::: "memory")
#define CP_WAIT1()  asm volatile("cp.async.wait_group 1;" ::: "memory")

// ===========================================================================
// Merged split kernel: fp32 -> bf16 hi/lo for q_x, w_qkv, w_g, w_o.
// ===========================================================================
__global__ __launch_bounds__(256) void k_split_all(
    const float* __restrict__ qx, const float* __restrict__ wqkv,
    const float* __restrict__ wg, const float* __restrict__ wo)
{
    const int bid = blockIdx.x;
    const float* src;
    __nv_bfloat16 *hi, *lo;
    size_t base;
    if (bid < 2048)      { src = qx;   hi = g_ahi;  lo = g_alo;  base = (size_t)bid; }
    else if (bid < 2816) { src = wqkv; hi = g_bhi;  lo = g_blo;  base = (size_t)(bid - 2048); }
    else if (bid < 3072) { src = wg;   hi = g_bhi + (size_t)1536 * 512;
                           lo = g_blo + (size_t)1536 * 512;      base = (size_t)(bid - 2816); }
    else                 { src = wo;   hi = g_wohi; lo = g_wolo; base = (size_t)(bid - 3072); }
    const size_t i = base * 256 + threadIdx.x;   // float4 index
    const float4 v = *(const float4*)(src + i * 4);
    uint2 hiw, low;
    hiw.x = pack_bf2(v.x, v.y);
    hiw.y = pack_bf2(v.z, v.w);
    low.x = pack_bf2(v.x - bf_lo(hiw.x), v.y - bf_hi(hiw.x));
    low.y = pack_bf2(v.z - bf_lo(hiw.y), v.w - bf_hi(hiw.y));
    *(uint2*)(hi + i * 4) = hiw;
    *(uint2*)(lo + i * 4) = low;
}

// ===========================================================================
// Shared bf16x3 HMMA GEMM mainloop, cp.async 3-stage pipelined (1 barrier/chunk).
// C[128m x 128n] += A[m][k]*B[n][k], K=512, chunks of 64.
// 256 thr = 8 warps (4m x 2n), warp tile 32m x 64n.
// smem: 3 stages x 64KB; stage: AH|AL|BH|BL (16KB each), swizzled 128B rows.
// ===========================================================================
#define G_STAGE 65536
#define G_SMEM  (3 * G_STAGE)

__device__ __forceinline__ void gemm_mainloop_db(
    const __nv_bfloat16* __restrict__ Ahi, const __nv_bfloat16* __restrict__ Alo,
    const __nv_bfloat16* __restrict__ Bhi, const __nv_bfloat16* __restrict__ Blo,
    int m0, int n0, char* smem, float acc[2][8][4])
{
    const uint32_t uS = smem_u32(smem);
    const int tid = threadIdx.x;
    const int warp = tid >> 5;
    const int lane = tid & 31;
    const int wm0 = (warp & 3) * 32;
    const int wn0 = (warp >> 2) * 64;
    const int lm = lane >> 3;
    const int lr = lane & 7;

#define G_ISSUE(s, kc) do { \
    const uint32_t _b = uS + (s) * G_STAGE; \
    _Pragma("unroll") \
    for (int _i = 0; _i < 4; ++_i) { \
        const int _a = tid + _i * 256; \
        const int _r = _a >> 3; \
        const int _g = _a & 7; \
        const uint32_t _so = SWZ((uint32_t)(_r * 128 + _g * 16)); \
        const size_t _ao = (size_t)(m0 + _r) * KDIM + (kc) + _g * 8; \
        const size_t _bo = (size_t)(n0 + _r) * KDIM + (kc) + _g * 8; \
        cpa16(_b + _so,         Ahi + _ao); \
        cpa16(_b + 16384 + _so, Alo + _ao); \
        cpa16(_b + 32768 + _so, Bhi + _bo); \
        cpa16(_b + 49152 + _so, Blo + _bo); \
    } } while (0)

    G_ISSUE(0, 0);  CP_COMMIT();
    G_ISSUE(1, 64); CP_COMMIT();

    for (int c = 0; c < 8; ++c) {
        CP_WAIT1();
        __syncthreads();     // all warps done with chunk c-1 -> stage (c+2)%3 free
        if (c + 2 < 8) {
            const int s = (c + 2) % 3;
            G_ISSUE(s, (c + 2) * 64);
        }
        CP_COMMIT();         // possibly empty: keeps wait_group invariant
        const uint32_t uAh = uS + (c % 3) * G_STAGE;
        const uint32_t uAl = uAh + 16384;
        const uint32_t uBh = uAh + 32768;
        const uint32_t uBl = uAh + 49152;

#pragma unroll
        for (int ks = 0; ks < 4; ++ks) {
            uint32_t ah[2][4], al[2][4];
#pragma unroll
            for (int i = 0; i < 2; ++i) {
                const int row = wm0 + 16 * i + ((lm & 1) ? 8 : 0) + lr;
                const int g = 2 * ks + (lm >> 1);
                const uint32_t off = SWZ((uint32_t)(row * 128 + g * 16));
                ldsm4(ah[i], uAh + off);
                ldsm4(al[i], uAl + off);
            }
#pragma unroll
            for (int jp = 0; jp < 4; ++jp) {
                const int nrow = wn0 + 16 * jp + ((lm >= 2) ? 8 : 0) + lr;
                const int g = 2 * ks + (lm & 1);
                const uint32_t off = SWZ((uint32_t)(nrow * 128 + g * 16));
                uint32_t bh[4], bl[4];
                ldsm4(bh, uBh + off);
                ldsm4(bl, uBl + off);
#pragma unroll
                for (int i = 0; i < 2; ++i) {
                    mma16816(acc[i][2 * jp],     ah[i], bh[0], bh[1]);
                    mma16816(acc[i][2 * jp + 1], ah[i], bh[2], bh[3]);
                    mma16816(acc[i][2 * jp],     ah[i], bl[0], bl[1]);
                    mma16816(acc[i][2 * jp + 1], ah[i], bl[2], bl[3]);
                    mma16816(acc[i][2 * jp],     al[i], bh[0], bh[1]);
                    mma16816(acc[i][2 * jp + 1], al[i], bh[2], bh[3]);
                }
            }
        }
    }
#undef G_ISSUE
}

// ===========================================================================
// Kernel 1: fused QKV + gate projection via HMMA bf16x3.
// q scaled by (1/8)*log2e (softmax runs in exp2 domain).
// ===========================================================================
__global__ __launch_bounds__(256) void k_gemm1_mma(const float* __restrict__ bg)
{
    extern __shared__ __align__(16) char smem[];
    const int m0 = blockIdx.y * 128;
    const int n0 = blockIdx.x * 128;

    float acc[2][8][4];
#pragma unroll
    for (int i = 0; i < 2; ++i)
#pragma unroll
        for (int j = 0; j < 8; ++j)
#pragma unroll
            for (int c = 0; c < 4; ++c) acc[i][j][c] = 0.f;

    gemm_mainloop_db(g_ahi, g_alo, g_bhi, g_blo, m0, n0, smem, acc);

    const int warp = threadIdx.x >> 5;
    const int lane = threadIdx.x & 31;
    const int wm0 = (warp & 3) * 32;
    const int wn0 = (warp >> 2) * 64;
    const int qrow = lane >> 2;
    const int nc = 2 * (lane & 3);

    const int region = n0 >> 9;   // 0=q, 1=k, 2=v, 3=gate
    const float qscale = (region == 0) ? (0.125f * LOG2E) : 1.0f;

#pragma unroll
    for (int i = 0; i < 2; ++i) {
        const int m = m0 + wm0 + 16 * i + qrow;
#pragma unroll
        for (int j = 0; j < 8; ++j) {
            const int n = n0 + wn0 + 8 * j + nc;
            float v0 = acc[i][j][0] * qscale, v1 = acc[i][j][1] * qscale;
            float v2 = acc[i][j][2] * qscale, v3 = acc[i][j][3] * qscale;
            if (region <= 1) {
                const uint32_t h0 = pack_bf2(v0, v1);
                const uint32_t l0 = pack_bf2(v0 - bf_lo(h0), v1 - bf_hi(h0));
                const uint32_t h1 = pack_bf2(v2, v3);
                const uint32_t l1 = pack_bf2(v2 - bf_lo(h1), v3 - bf_hi(h1));
                const size_t i0 = (size_t)m * 512 + (n - region * 512);
                const size_t i1 = i0 + (size_t)8 * 512;
                if (region == 0) {
                    *(uint32_t*)(&g_qhi[i0]) = h0; *(uint32_t*)(&g_qlo[i0]) = l0;
                    *(uint32_t*)(&g_qhi[i1]) = h1; *(uint32_t*)(&g_qlo[i1]) = l1;
                } else {
                    *(uint32_t*)(&g_khi[i0]) = h0; *(uint32_t*)(&g_klo[i0]) = l0;
                    *(uint32_t*)(&g_khi[i1]) = h1; *(uint32_t*)(&g_klo[i1]) = l1;
                }
            } else {
                if (region == 3) {
                    const float b0v = bg[n - 1536], b1v = bg[n - 1535];
                    v0 = 1.0f / (1.0f + __expf(-(v0 + b0v)));
                    v1 = 1.0f / (1.0f + __expf(-(v1 + b1v)));
                    v2 = 1.0f / (1.0f + __expf(-(v2 + b0v)));
                    v3 = 1.0f / (1.0f + __expf(-(v3 + b1v)));
                }
                *(float2*)(&g_qkvg[(size_t)m * NCOLS + n]) = make_float2(v0, v1);
                *(float2*)(&g_qkvg[(size_t)(m + 8) * NCOLS + n]) = make_float2(v2, v3);
            }
        }
    }
}

// ===========================================================================
// Kernel 1b: V transpose + bf16 hi/lo split.  [token][d] fp32 -> [b,h][d][token]
// ===========================================================================
__global__ __launch_bounds__(256) void k_vsplit()
{
    __shared__ float t[128][65];
    const int tid = threadIdx.x;
    const int tok0 = blockIdx.x * 128;
    const int h = blockIdx.y;
    const int b = blockIdx.z;
    const size_t rbase = (size_t)b * QQ;

#pragma unroll
    for (int i = 0; i < 8; ++i) {
        const int a = tid + i * 256;
        const int r = a >> 4;
        const int c = (a & 15) * 4;
        const float4 v = *(const float4*)(&g_qkvg[(rbase + tok0 + r) * NCOLS + 1024 + h * HD + c]);
        t[r][c + 0] = v.x; t[r][c + 1] = v.y; t[r][c + 2] = v.z; t[r][c + 3] = v.w;
    }
    __syncthreads();

    const int d = tid >> 2;
    const int tq = (tid & 3) * 32;
    uint32_t hiw[16], low[16];
#pragma unroll
    for (int j = 0; j < 16; ++j) {
        const float x0 = t[tq + 2 * j][d];
        const float x1 = t[tq + 2 * j + 1][d];
        const uint32_t ph = pack_bf2(x0, x1);
        hiw[j] = ph;
        low[j] = pack_bf2(x0 - bf_lo(ph), x1 - bf_hi(ph));
    }
    const size_t dst = ((size_t)(b * NH + h) * HD + d) * QQ + tok0 + tq;
#pragma unroll
    for (int j = 0; j < 4; ++j) {
        *(uint4*)(&g_vthi[dst + j * 8]) = make_uint4(hiw[4*j], hiw[4*j+1], hiw[4*j+2], hiw[4*j+3]);
        *(uint4*)(&g_vtlo[dst + j * 8]) = make_uint4(low[4*j], low[4*j+1], low[4*j+2], low[4*j+3]);
    }
}

// ===========================================================================
// Kernel 2: flash attention, bf16x3 HMMA, cp.async 3-stage K/V pipeline.
// FQT=64 q-rows, 128 thr = 4 warps x 16 rows -> 2 CTAs/SM.
// smem 112KB: Q (QH|QL, 16KB) + 3 stages x 32KB (KH|KL|VH|VL).
// Bias folded into S-accumulator init (x log2e); softmax in exp2 domain.
// ===========================================================================
#define FQT 64
#define FKT 64
#define F_NT (QQ / FKT)
#define F_STAGE0 16384
#define F_STAGE 32768
#define F_TOTAL (F_STAGE0 + 3 * F_STAGE)   // 114688

__global__ __launch_bounds__(128) void k_flash_mma(const float* __restrict__ bias)
{
    extern __shared__ __align__(16) char smem[];
    const uint32_t uS = smem_u32(smem);

    const int tid  = threadIdx.x;
    const int warp = tid >> 5;
    const int lane = tid & 31;
    const int q0 = blockIdx.x * FQT;
    const int h  = blockIdx.y;
    const int b  = blockIdx.z;

    const size_t rbase = (size_t)b * QQ;
    const int hq = h * HD;
    const size_t vtb = (size_t)(b * NH + h) * HD;

#define F_ISSUE(s, k0) do { \
    const uint32_t _b = uS + F_STAGE0 + (s) * F_STAGE; \
    _Pragma("unroll") \
    for (int _i = 0; _i < 4; ++_i) { \
        const int _a = tid + _i * 128; \
        const int _r = _a >> 3; \
        const int _g = _a & 7; \
        const uint32_t _so = SWZ((uint32_t)(_r * 128 + _g * 16)); \
        const size_t _ko = (rbase + (k0) + _r) * 512 + hq + _g * 8; \
        const size_t _vo = (vtb + _r) * QQ + (k0) + _g * 8; \
        cpa16(_b + _so,         g_khi + _ko); \
        cpa16(_b + 8192 + _so,  g_klo + _ko); \
        cpa16(_b + 16384 + _so, g_vthi + _vo); \
        cpa16(_b + 24576 + _so, g_vtlo + _vo); \
    } } while (0)

    // prologue: start K/V tiles 0,1 streaming, then stage Q
    F_ISSUE(0, 0);   CP_COMMIT();
    F_ISSUE(1, FKT); CP_COMMIT();

    char* sQh = smem;
    char* sQl = smem + 8192;
#pragma unroll
    for (int i = 0; i < 4; ++i) {
        const int a = tid + i * 128;
        const int r = a >> 3;
        const int g = a & 7;
        const size_t src = (rbase + q0 + r) * 512 + hq + g * 8;
        const uint32_t so = SWZ((uint32_t)(r * 128 + g * 16));
        *(uint4*)(sQh + so) = *(const uint4*)(&g_qhi[src]);
        *(uint4*)(sQl + so) = *(const uint4*)(&g_qlo[src]);
    }
    __syncthreads();

    const int lm = lane >> 3;
    const int lr = lane & 7;
    const uint32_t uQh = uS, uQl = uS + 8192;
    uint32_t qh[4][4], ql[4][4];
#pragma unroll
    for (int ks = 0; ks < 4; ++ks) {
        const int row = warp * 16 + ((lm & 1) ? 8 : 0) + lr;
        const int g = 2 * ks + (lm >> 1);
        const uint32_t off = SWZ((uint32_t)(row * 128 + g * 16));
        ldsm4(qh[ks], uQh + off);
        ldsm4(ql[ks], uQl + off);
    }

    const int qrow = lane >> 2;
    const float* biasb = bias + (size_t)b * QQ * QQ;
    const float* bp0 = biasb + (size_t)(q0 + warp * 16 + qrow) * QQ + 2 * (lane & 3);
    const float* bp1 = bp0 + 8 * QQ;

    float oacc[8][4];
#pragma unroll
    for (int j = 0; j < 8; ++j)
#pragma unroll
        for (int c = 0; c < 4; ++c) oacc[j][c] = 0.f;
    float mrow0 = -3.0e38f, mrow1 = -3.0e38f, lrow0 = 0.f, lrow1 = 0.f;

    for (int kt = 0; kt < F_NT; ++kt) {
        const int k0 = kt * FKT;
        CP_WAIT1();
        __syncthreads();   // all warps done with tile kt-1 -> stage (kt+2)%3 free
        if (kt + 2 < F_NT) {
            const int s = (kt + 2) % 3;
            F_ISSUE(s, (kt + 2) * FKT);
        }
        CP_COMMIT();       // possibly empty
        const uint32_t uKh = uS + F_STAGE0 + (kt % 3) * F_STAGE;
        const uint32_t uKl = uKh + 8192;
        const uint32_t uVh = uKh + 16384;
        const uint32_t uVl = uKh + 24576;

        // ---- S accumulators initialized with bias*log2e (loads hidden by MMA) ----
        float sacc[8][4];
#pragma unroll
        for (int jt = 0; jt < 8; ++jt) {
            const float2 b0v = *(const float2*)(bp0 + k0 + 8 * jt);
            const float2 b1v = *(const float2*)(bp1 + k0 + 8 * jt);
            sacc[jt][0] = b0v.x * LOG2E; sacc[jt][1] = b0v.y * LOG2E;
            sacc[jt][2] = b1v.x * LOG2E; sacc[jt][3] = b1v.y * LOG2E;
        }

        // ---- S = Q K^T (bf16x3), already in exp2 domain ----
#pragma unroll
        for (int ks = 0; ks < 4; ++ks) {
#pragma unroll
            for (int jp = 0; jp < 4; ++jp) {
                const int tok = 16 * jp + ((lm >= 2) ? 8 : 0) + lr;
                const int g = 2 * ks + (lm & 1);
                const uint32_t off = SWZ((uint32_t)(tok * 128 + g * 16));
                uint32_t kh[4], kl[4];
                ldsm4(kh, uKh + off);
                ldsm4(kl, uKl + off);
                mma16816(sacc[2 * jp],     qh[ks], kh[0], kh[1]);
                mma16816(sacc[2 * jp + 1], qh[ks], kh[2], kh[3]);
                mma16816(sacc[2 * jp],     qh[ks], kl[0], kl[1]);
                mma16816(sacc[2 * jp + 1], qh[ks], kl[2], kl[3]);
                mma16816(sacc[2 * jp],     ql[ks], kh[0], kh[1]);
                mma16816(sacc[2 * jp + 1], ql[ks], kh[2], kh[3]);
            }
        }

        // ---- online softmax (exp2 domain; rows qrow, qrow+8; quad reduce) ----
        float mx0 = sacc[0][0], mx1 = sacc[0][2];
#pragma unroll
        for (int jt = 0; jt < 8; ++jt) {
            mx0 = fmaxf(mx0, fmaxf(sacc[jt][0], sacc[jt][1]));
            mx1 = fmaxf(mx1, fmaxf(sacc[jt][2], sacc[jt][3]));
        }
        mx0 = fmaxf(mx0, __shfl_xor_sync(0xffffffffu, mx0, 1));
        mx0 = fmaxf(mx0, __shfl_xor_sync(0xffffffffu, mx0, 2));
        mx1 = fmaxf(mx1, __shfl_xor_sync(0xffffffffu, mx1, 1));
        mx1 = fmaxf(mx1, __shfl_xor_sync(0xffffffffu, mx1, 2));
        const float mn0 = fmaxf(mrow0, mx0);
        const float mn1 = fmaxf(mrow1, mx1);
        const float sc0 = ex2(mrow0 - mn0);
        const float sc1 = ex2(mrow1 - mn1);
        float ls0 = 0.f, ls1 = 0.f;
#pragma unroll
        for (int jt = 0; jt < 8; ++jt) {
            sacc[jt][0] = ex2(sacc[jt][0] - mn0);
            sacc[jt][1] = ex2(sacc[jt][1] - mn0);
            sacc[jt][2] = ex2(sacc[jt][2] - mn1);
            sacc[jt][3] = ex2(sacc[jt][3] - mn1);
            ls0 += sacc[jt][0] + sacc[jt][1];
            ls1 += sacc[jt][2] + sacc[jt][3];
        }
        ls0 += __shfl_xor_sync(0xffffffffu, ls0, 1);
        ls0 += __shfl_xor_sync(0xffffffffu, ls0, 2);
        ls1 += __shfl_xor_sync(0xffffffffu, ls1, 1);
        ls1 += __shfl_xor_sync(0xffffffffu, ls1, 2);
        lrow0 = lrow0 * sc0 + ls0;
        lrow1 = lrow1 * sc1 + ls1;
        mrow0 = mn0;
        mrow1 = mn1;
#pragma unroll
        for (int j = 0; j < 8; ++j) {
            oacc[j][0] *= sc0; oacc[j][1] *= sc0;
            oacc[j][2] *= sc1; oacc[j][3] *= sc1;
        }

        // ---- PV (bf16x3; P register-only via C->A frag identity) ----
#pragma unroll
        for (int ks = 0; ks < 4; ++ks) {
            uint32_t ph[4], pl[4];
#pragma unroll
            for (int half = 0; half < 2; ++half) {
                const float x0 = sacc[2 * ks + half][0], x1 = sacc[2 * ks + half][1];
                const float y0 = sacc[2 * ks + half][2], y1 = sacc[2 * ks + half][3];
                const uint32_t p0 = pack_bf2(x0, x1);
                const uint32_t p1 = pack_bf2(y0, y1);
                ph[2 * half + 0] = p0;
                ph[2 * half + 1] = p1;
                pl[2 * half + 0] = pack_bf2(x0 - bf_lo(p0), x1 - bf_hi(p0));
                pl[2 * half + 1] = pack_bf2(y0 - bf_lo(p1), y1 - bf_hi(p1));
            }
#pragma unroll
            for (int jdp = 0; jdp < 4; ++jdp) {
                const int d = 16 * jdp + ((lm >= 2) ? 8 : 0) + lr;
                const int g = 2 * ks + (lm & 1);
                const uint32_t off = SWZ((uint32_t)(d * 128 + g * 16));
                uint32_t vh[4], vl[4];
                ldsm4(vh, uVh + off);
                ldsm4(vl, uVl + off);
                mma16816(oacc[2 * jdp],     ph, vh[0], vh[1]);
                mma16816(oacc[2 * jdp + 1], ph, vh[2], vh[3]);
                mma16816(oacc[2 * jdp],     ph, vl[0], vl[1]);
                mma16816(oacc[2 * jdp + 1], ph, vl[2], vl[3]);
                mma16816(oacc[2 * jdp],     pl, vh[0], vh[1]);
                mma16816(oacc[2 * jdp + 1], pl, vh[2], vh[3]);
            }
        }
    }
#undef F_ISSUE

    // ---- epilogue: normalize + sigmoid gate -> split-bf16 o ----
    {
        const float inv0 = 1.0f / lrow0;
        const float inv1 = 1.0f / lrow1;
        const size_t row0 = rbase + q0 + warp * 16 + qrow;
        const size_t row1 = row0 + 8;
        const int dcol = 2 * (lane & 3);
#pragma unroll
        for (int jd = 0; jd < 8; ++jd) {
            const int d = 8 * jd + dcol;
            const float2 g0 = *(const float2*)(&g_qkvg[row0 * NCOLS + 1536 + hq + d]);
            const float2 g1 = *(const float2*)(&g_qkvg[row1 * NCOLS + 1536 + hq + d]);
            const float o0x = oacc[jd][0] * inv0 * g0.x;
            const float o0y = oacc[jd][1] * inv0 * g0.y;
            const float o1x = oacc[jd][2] * inv1 * g1.x;
            const float o1y = oacc[jd][3] * inv1 * g1.y;
            const uint32_t h0 = pack_bf2(o0x, o0y);
            const uint32_t l0 = pack_bf2(o0x - bf_lo(h0), o0y - bf_hi(h0));
            const uint32_t h1 = pack_bf2(o1x, o1y);
            const uint32_t l1 = pack_bf2(o1x - bf_lo(h1), o1y - bf_hi(h1));
            *(uint32_t*)(&g_ohi[row0 * 512 + hq + d]) = h0;
            *(uint32_t*)(&g_olo[row0 * 512 + hq + d]) = l0;
            *(uint32_t*)(&g_ohi[row1 * 512 + hq + d]) = h1;
            *(uint32_t*)(&g_olo[row1 * 512 + hq + d]) = l1;
        }
    }
}

// ===========================================================================
// Kernel 3: output projection via HMMA bf16x3
// ===========================================================================
__global__ __launch_bounds__(256) void k_gemm2_mma(
    const float* __restrict__ bo, float* __restrict__ out)
{
    extern __shared__ __align__(16) char smem[];
    const int m0 = blockIdx.y * 128;
    const int n0 = blockIdx.x * 128;

    float acc[2][8][4];
#pragma unroll
    for (int i = 0; i < 2; ++i)
#pragma unroll
        for (int j = 0; j < 8; ++j)
#pragma unroll
            for (int c = 0; c < 4; ++c) acc[i][j][c] = 0.f;

    gemm_mainloop_db(g_ohi, g_olo, g_wohi, g_wolo, m0, n0, smem, acc);

    const int warp = threadIdx.x >> 5;
    const int lane = threadIdx.x & 31;
    const int wm0 = (warp & 3) * 32;
    const int wn0 = (warp >> 2) * 64;
    const int qrow = lane >> 2;
    const int nc = 2 * (lane & 3);

#pragma unroll
    for (int i = 0; i < 2; ++i) {
        const int m = m0 + wm0 + 16 * i + qrow;
#pragma unroll
        for (int j = 0; j < 8; ++j) {
            const int n = n0 + wn0 + 8 * j + nc;
            const float b0v = bo[n], b1v = bo[n + 1];
            *(float2*)(&out[(size_t)m * 512 + n]) =
                make_float2(acc[i][j][0] + b0v, acc[i][j][1] + b1v);
            *(float2*)(&out[(size_t)(m + 8) * 512 + n]) =
                make_float2(acc[i][j][2] + b0v, acc[i][j][3] + b1v);
        }
    }
}

// ---------------------------------------------------------------------------
extern "C" void kernel_launch(void* const* d_in, const int* in_sizes, int n_in,
                              void* d_out, int out_size)
{
    (void)in_sizes; (void)n_in; (void)out_size;
    const float* q_x   = (const float*)d_in[0];
    // d_in[1] = kv_x (unused by the reference)
    const float* bias  = (const float*)d_in[2];
    const float* w_qkv = (const float*)d_in[3];
    const float* w_o   = (const float*)d_in[4];
    const float* b_o   = (const float*)d_in[5];
    const float* w_g   = (const float*)d_in[6];
    const float* b_g   = (const float*)d_in[7];
    float* out = (float*)d_out;

    cudaFuncSetAttribute(k_flash_mma, cudaFuncAttributeMaxDynamicSharedMemorySize,
                         (int)F_TOTAL);
    cudaFuncSetAttribute(k_gemm1_mma, cudaFuncAttributeMaxDynamicSharedMemorySize,
                         (int)G_SMEM);
    cudaFuncSetAttribute(k_gemm2_mma, cudaFuncAttributeMaxDynamicSharedMemorySize,
                         (int)G_SMEM);

    k_split_all<<<3328, 256>>>(q_x, w_qkv, w_g, w_o);

    dim3 g1(NCOLS / 128, MROWS / 128);  // (16, 32)
    k_gemm1_mma<<<g1, 256, G_SMEM>>>(b_g);

    dim3 gv(QQ / 128, NH, BB);          // (16, 8, 2)
    k_vsplit<<<gv, 256>>>();

    dim3 g2(QQ / FQT, NH, BB);          // (32, 8, 2)
    k_flash_mma<<<g2, 128, F_TOTAL>>>(bias);

    dim3 g3(512 / 128, MROWS / 128);    // (4, 32)
    k_gemm2_mma<<<g3, 256, G_SMEM>>>(b_o, out);
}